// round 3
// baseline (speedup 1.0000x reference)
#include <cuda_runtime.h>
#include <cuda_bf16.h>

// Problem constants (from reference): B=8, N=2048, D=512, S=4096
#define PB 8
#define PN 2048
#define PD 512
#define PS 4096
#define NROWS (PB * PS)        // 32768 total swap rows
#define K1 (4 * PD)            // 2048 (GEMM1 K)
#define N1 PD                  // 512  (GEMM1 N)
#define K2 PD                  // 512  (GEMM2 K)
#define N2 (PD / 2)            // 256  (GEMM2 N)

#define ROWS_PER_CTA 32
#define SMEM_FLOATS 25252
#define SMEM_BYTES (SMEM_FLOATS * 4)

__device__ __forceinline__ float gelu_exact(float x) {
    return 0.5f * x * (1.0f + erff(x * 0.70710678118654752440f));
}

__device__ __forceinline__ float softplus_stable(float x) {
    return fmaxf(x, 0.0f) + log1pf(expf(-fabsf(x)));
}

// ============================================================================
// Fully fused: gather -> GEMM1+GELU (smem-resident x1) -> GEMM2+GELU ->
// dot(W3)+b3 -> softplus. One CTA owns 32 swap rows. No global scratch.
// ============================================================================
__global__ void __launch_bounds__(256, 2)
swap_scoring_fused(const float* __restrict__ h,
                   const void* __restrict__ indices_raw,
                   const float* __restrict__ W1,
                   const float* __restrict__ b1,
                   const float* __restrict__ W2,
                   const float* __restrict__ b2,
                   const float* __restrict__ W3,
                   const float* __restrict__ b3,
                   float* __restrict__ out)
{
    extern __shared__ float sm[];
    float* x1s = sm;                   // [32][512]  65536 B
    float* As1 = sm + 16384;           // [16][32]
    float* Bs1 = As1 + 512;            // [16][128]
    float* Bs2 = Bs1 + 2048;           // [16][256]
    float* b1s = Bs2 + 4096;           // [512]
    float* b2s = b1s + 512;            // [256]
    float* w3s = b2s + 256;            // [256]
    float* red = w3s + 256;            // [32][33]
    int*   off = (int*)(red + 1056);   // [32][4]
    int*   smode = (int*)(off + 128);  // [1]

    const int tid  = threadIdx.x;
    const int row0 = blockIdx.x * ROWS_PER_CTA;
    const int b    = row0 / PS;
    const int s0   = row0 % PS;

    // --- Detect index dtype: int64-LE has all odd 32-bit words == 0 ---
    if (tid == 0) {
        const int* p32 = (const int*)indices_raw;
        int is64 = 1;
        #pragma unroll
        for (int t = 0; t < 32; t++)       // probes words 1,3,..,63: in-bounds
            if (p32[2 * t + 1] != 0) { is64 = 0; break; }
        smode[0] = is64;
    }

    // Stage biases / W3
    for (int i = tid; i < 512; i += 256) b1s[i] = b1[i];
    b2s[tid & 255] = b2[tid & 255];
    w3s[tid & 255] = W3[tid & 255];
    __syncthreads();

    // Gather base offsets (masked: identity for valid data, never wild)
    if (tid < ROWS_PER_CTA * 4) {
        const int  m = tid >> 2, j = tid & 3;
        const long long e = ((long long)(b * PS + s0 + m)) * 4 + j;
        int idx;
        if (smode[0]) idx = (int)((const long long*)indices_raw)[e];
        else          idx = ((const int*)indices_raw)[e];
        off[m * 4 + j] = (b * PN + (idx & (PN - 1))) * PD;
    }
    __syncthreads();

    // ---------------- Phase 1: x1 = gelu(gather(h) @ W1 + b1) ----------------
    // Thread microtile: 2 rows x 8 cols (cols split tn4 / tn4+64)
    const int tm2 = (tid >> 4) * 2;      // 0..30
    const int tn4 = (tid & 15) * 4;      // 0..60

    #pragma unroll 1
    for (int nc = 0; nc < 4; ++nc) {
        const int colBase = nc * 128;
        float c1[2][8];
        #pragma unroll
        for (int i = 0; i < 2; i++)
            #pragma unroll
            for (int q = 0; q < 8; q++) c1[i][q] = 0.0f;

        #pragma unroll 1
        for (int kt = 0; kt < K1; kt += 16) {
            // Prefetch A (gathered) — 128 threads, float4 each
            float4 aR;
            const int ar = tid >> 2;
            const int ak = (tid & 3) << 2;
            if (tid < 128) {
                const int j = kt >> 9;   // 16-deep K tile never straddles a 512 block
                aR = *(const float4*)(h + off[ar * 4 + j] + (kt & (PD - 1)) + ak);
            }
            // Prefetch B (W1 chunk) — 256 threads, 8 floats each
            const int bk = tid >> 4;             // 0..15
            const int bn = (tid & 15) * 8;       // 0..120
            const float* wp = W1 + (size_t)(kt + bk) * N1 + colBase + bn;
            const float4 bR0 = *(const float4*)(wp);
            const float4 bR1 = *(const float4*)(wp + 4);

            __syncthreads();   // previous tile fully consumed
            if (tid < 128) {
                As1[(ak + 0) * 32 + ar] = aR.x;
                As1[(ak + 1) * 32 + ar] = aR.y;
                As1[(ak + 2) * 32 + ar] = aR.z;
                As1[(ak + 3) * 32 + ar] = aR.w;
            }
            *(float4*)&Bs1[bk * 128 + bn]     = bR0;
            *(float4*)&Bs1[bk * 128 + bn + 4] = bR1;
            __syncthreads();

            #pragma unroll
            for (int kk = 0; kk < 16; ++kk) {
                const float2 a  = *(const float2*)&As1[kk * 32 + tm2];
                const float4 b0 = *(const float4*)&Bs1[kk * 128 + tn4];
                const float4 b4 = *(const float4*)&Bs1[kk * 128 + tn4 + 64];
                const float av[2] = {a.x, a.y};
                const float bv[8] = {b0.x, b0.y, b0.z, b0.w, b4.x, b4.y, b4.z, b4.w};
                #pragma unroll
                for (int i = 0; i < 2; i++)
                    #pragma unroll
                    for (int q = 0; q < 8; q++)
                        c1[i][q] = fmaf(av[i], bv[q], c1[i][q]);
            }
        }

        // Epilogue: bias + exact GELU -> smem x1 tile
        #pragma unroll
        for (int i = 0; i < 2; i++) {
            const int r = tm2 + i;
            float4 v0, v1;
            v0.x = gelu_exact(c1[i][0] + b1s[colBase + tn4 + 0]);
            v0.y = gelu_exact(c1[i][1] + b1s[colBase + tn4 + 1]);
            v0.z = gelu_exact(c1[i][2] + b1s[colBase + tn4 + 2]);
            v0.w = gelu_exact(c1[i][3] + b1s[colBase + tn4 + 3]);
            v1.x = gelu_exact(c1[i][4] + b1s[colBase + tn4 + 64]);
            v1.y = gelu_exact(c1[i][5] + b1s[colBase + tn4 + 65]);
            v1.z = gelu_exact(c1[i][6] + b1s[colBase + tn4 + 66]);
            v1.w = gelu_exact(c1[i][7] + b1s[colBase + tn4 + 67]);
            *(float4*)&x1s[r * N1 + colBase + tn4]      = v0;
            *(float4*)&x1s[r * N1 + colBase + tn4 + 64] = v1;
        }
    }
    __syncthreads();

    // ---------------- Phase 2: y = gelu(x1 @ W2 + b2); out = softplus(y.W3+b3)
    // Thread microtile: 4 rows x 8 cols (cols split 4*tx / 4*tx+128)
    const int ty = tid >> 5;   // 0..7 -> rows 4*ty..4*ty+3
    const int tx = tid & 31;   // cols 4*tx.. and 128+4*tx..
    float c2[4][8];
    #pragma unroll
    for (int i = 0; i < 4; i++)
        #pragma unroll
        for (int q = 0; q < 8; q++) c2[i][q] = 0.0f;

    #pragma unroll 1
    for (int kt = 0; kt < K2; kt += 16) {
        // Prefetch W2 tile 16x256 — 16 floats/thread
        const int bk = tid >> 4;            // 0..15
        const int bn = (tid & 15) * 16;     // 0..240
        const float* wp = W2 + (size_t)(kt + bk) * N2 + bn;
        const float4 r0 = *(const float4*)(wp);
        const float4 r1 = *(const float4*)(wp + 4);
        const float4 r2 = *(const float4*)(wp + 8);
        const float4 r3 = *(const float4*)(wp + 12);

        __syncthreads();
        *(float4*)&Bs2[bk * 256 + bn]      = r0;
        *(float4*)&Bs2[bk * 256 + bn + 4]  = r1;
        *(float4*)&Bs2[bk * 256 + bn + 8]  = r2;
        *(float4*)&Bs2[bk * 256 + bn + 12] = r3;
        __syncthreads();

        #pragma unroll
        for (int kk = 0; kk < 16; ++kk) {
            float av[4];
            #pragma unroll
            for (int i = 0; i < 4; i++)
                av[i] = x1s[(4 * ty + i) * N1 + kt + kk];   // warp-broadcast
            const float4 b0 = *(const float4*)&Bs2[kk * 256 + 4 * tx];
            const float4 b4 = *(const float4*)&Bs2[kk * 256 + 4 * tx + 128];
            const float bv[8] = {b0.x, b0.y, b0.z, b0.w, b4.x, b4.y, b4.z, b4.w};
            #pragma unroll
            for (int i = 0; i < 4; i++)
                #pragma unroll
                for (int q = 0; q < 8; q++)
                    c2[i][q] = fmaf(av[i], bv[q], c2[i][q]);
        }
    }

    // Epilogue: gelu(+b2) dot W3, reduce 32 partials per row, softplus
    const float b3v = b3[0];
    #pragma unroll
    for (int i = 0; i < 4; i++) {
        float p = 0.0f;
        #pragma unroll
        for (int q = 0; q < 4; q++) {
            const int col = 4 * tx + q;
            p = fmaf(gelu_exact(c2[i][q] + b2s[col]), w3s[col], p);
        }
        #pragma unroll
        for (int q = 4; q < 8; q++) {
            const int col = 128 + 4 * tx + (q - 4);
            p = fmaf(gelu_exact(c2[i][q] + b2s[col]), w3s[col], p);
        }
        red[(4 * ty + i) * 33 + tx] = p;
    }
    __syncthreads();

    if (tid < ROWS_PER_CTA) {
        float s = 0.0f;
        #pragma unroll
        for (int t = 0; t < 32; t++) s += red[tid * 33 + t];
        out[row0 + tid] = softplus_stable(s + b3v);
    }
}

extern "C" void kernel_launch(void* const* d_in, const int* in_sizes, int n_in,
                              void* d_out, int out_size)
{
    const float* h   = (const float*)d_in[0];
    const void*  idx = (const void*)d_in[1];
    const float* W1  = (const float*)d_in[2];
    const float* b1  = (const float*)d_in[3];
    const float* W2  = (const float*)d_in[4];
    const float* b2  = (const float*)d_in[5];
    const float* W3  = (const float*)d_in[6];
    const float* b3  = (const float*)d_in[7];
    float*       out = (float*)d_out;

    cudaFuncSetAttribute(swap_scoring_fused,
                         cudaFuncAttributeMaxDynamicSharedMemorySize, SMEM_BYTES);
    swap_scoring_fused<<<NROWS / ROWS_PER_CTA, 256, SMEM_BYTES>>>(
        h, idx, W1, b1, W2, b2, W3, b3, out);
}

// round 5
// speedup vs baseline: 4.1463x; 4.1463x over previous
#include <cuda_runtime.h>
#include <cstdint>

// Problem: B=8, N=2048, D=512, S=4096
#define PB 8
#define PN 2048
#define PD 512
#define PS 4096
#define NROWS 32768
#define K1 2048
#define N1 512
#define K2 512
#define N2 256

#define MTILE 64
#define KC 16

// ---- tf32-rounded copies (device scratch; allowed per rules) ----
__device__ float g_h[PB * PN * PD];     // 33.5 MB
__device__ float g_W1[K1 * N1];         // 4 MB
__device__ float g_W2[K2 * N2];         // 0.5 MB

// ---- smem layout (floats) ----
#define FX1   0                          // x1s [64][516]
#define FAS0  33024                      // A tile buf0 [64][36]
#define FAS1  35328
#define FBS0  37632                      // B tile buf0 [16][520]
#define FBS1  45952
#define FB1S  54272                      // b1 [512]
#define FB2S  54784                      // b2 [256]
#define FW3S  55040                      // W3 [256]
#define FRED  55296                      // red [64][4]
#define FOFF  55552                      // off [64][4] ints
#define FMODE 55808
#define SMEM_FLOATS 55812
#define SMEM_BYTES (SMEM_FLOATS * 4)

__device__ __forceinline__ float to_tf32(float x) {
    uint32_t u;
    asm("cvt.rna.tf32.f32 %0, %1;" : "=r"(u) : "f"(x));
    return __uint_as_float(u);
}
__device__ __forceinline__ float gelu_exact(float x) {
    return 0.5f * x * (1.0f + erff(x * 0.70710678118654752440f));
}
__device__ __forceinline__ float softplus_stable(float x) {
    return fmaxf(x, 0.0f) + log1pf(expf(-fabsf(x)));
}
__device__ __forceinline__ uint32_t smem_u32(const void* p) {
    uint32_t a;
    asm("{ .reg .u64 t; cvta.to.shared.u64 t, %1; cvt.u32.u64 %0, t; }" : "=r"(a) : "l"(p));
    return a;
}
__device__ __forceinline__ void cp16(uint32_t dst, const void* src) {
    asm volatile("cp.async.cg.shared.global [%0], [%1], 16;" :: "r"(dst), "l"(src));
}
#define CP_COMMIT() asm volatile("cp.async.commit_group;" ::: "memory")
#define CP_WAIT(n)  asm volatile("cp.async.wait_group %0;" :: "n"(n) : "memory")

__device__ __forceinline__ void mma_tf32(float* d, const uint32_t* a, const uint32_t* b) {
    asm volatile(
        "mma.sync.aligned.m16n8k8.row.col.f32.tf32.tf32.f32 "
        "{%0,%1,%2,%3}, {%4,%5,%6,%7}, {%8,%9}, {%0,%1,%2,%3};"
        : "+f"(d[0]), "+f"(d[1]), "+f"(d[2]), "+f"(d[3])
        : "r"(a[0]), "r"(a[1]), "r"(a[2]), "r"(a[3]), "r"(b[0]), "r"(b[1]));
}

// ---- prepass: round arrays to tf32 ----
__global__ void cvt_tf32_kernel(float* __restrict__ dst, const float* __restrict__ src, int n4) {
    for (int i = blockIdx.x * blockDim.x + threadIdx.x; i < n4; i += gridDim.x * blockDim.x) {
        float4 v = ((const float4*)src)[i];
        v.x = to_tf32(v.x); v.y = to_tf32(v.y); v.z = to_tf32(v.z); v.w = to_tf32(v.w);
        ((float4*)dst)[i] = v;
    }
}

// ============================================================================
__global__ void __launch_bounds__(256, 1)
swap_scoring_mma(const float* __restrict__ hraw,   // only for dtype-detect symmetry (unused)
                 const void* __restrict__ indices_raw,
                 const float* __restrict__ b1,
                 const float* __restrict__ b2,
                 const float* __restrict__ W3,
                 const float* __restrict__ b3,
                 float* __restrict__ out)
{
    extern __shared__ float sm[];
    float* x1s = sm + FX1;
    float* Asb[2] = { sm + FAS0, sm + FAS1 };
    float* Bsb[2] = { sm + FBS0, sm + FBS1 };
    float* b1s = sm + FB1S;
    float* b2s = sm + FB2S;
    float* w3s = sm + FW3S;
    float* red = sm + FRED;
    int*   off = (int*)(sm + FOFF);

    const uint32_t sb = smem_u32(sm);
    const uint32_t AsA[2] = { sb + FAS0 * 4, sb + FAS1 * 4 };
    const uint32_t BsA[2] = { sb + FBS0 * 4, sb + FBS1 * 4 };

    const int tid  = threadIdx.x;
    const int lane = tid & 31;
    const int wid  = tid >> 5;
    const int lq   = lane >> 2;      // 0..7
    const int lr   = lane & 3;       // 0..3
    const int wm   = wid >> 2;       // 0..1
    const int wn   = wid & 3;        // 0..3

    const int row0 = blockIdx.x * MTILE;
    const int bb   = row0 / PS;
    const int s0   = row0 % PS;

    // dtype detection (int64-LE => all odd 32-bit words zero; proven in R3)
    if (tid == 0) {
        const int* p32 = (const int*)indices_raw;
        int is64 = 1;
        #pragma unroll
        for (int t = 0; t < 32; t++)
            if (p32[2 * t + 1] != 0) { is64 = 0; break; }
        *(int*)(sm + FMODE) = is64;
    }
    for (int i = tid; i < 512; i += 256) b1s[i] = b1[i];
    if (tid < 256) { b2s[tid] = b2[tid]; w3s[tid] = W3[tid]; }
    __syncthreads();

    const int is64 = *(const int*)(sm + FMODE);
    if (tid < MTILE * 4) {
        const int m = tid >> 2, j = tid & 3;
        const long long e = ((long long)(bb * PS + s0 + m)) * 4 + j;
        int idx;
        if (is64) idx = (int)((const long long*)indices_raw)[e];
        else      idx = ((const int*)indices_raw)[e];
        off[m * 4 + j] = (bb * PN + (idx & (PN - 1))) * PD;
    }
    __syncthreads();

    // ======================= Phase 1: x1 = gelu(A@W1+b1) =====================
    float acc[2][16][4];
    #pragma unroll
    for (int mf = 0; mf < 2; mf++)
        #pragma unroll
        for (int nf = 0; nf < 16; nf++)
            #pragma unroll
            for (int q = 0; q < 4; q++) acc[mf][nf][q] = 0.0f;

    const int S1 = K1 / KC;   // 128

    // stage 0
    {
        const int row = tid >> 2, kq = (tid & 3) * 4;
        cp16(AsA[0] + (row * 36 + kq) * 4, g_h + off[row * 4 + 0] + 0 + kq);
        #pragma unroll
        for (int i = 0; i < 8; i++) {
            const int slot = i * 256 + tid;
            const int kk = slot >> 7, nq = (slot & 127) * 4;
            cp16(BsA[0] + (kk * 520 + nq) * 4, g_W1 + (size_t)kk * N1 + nq);
        }
        CP_COMMIT();
    }

    for (int s = 0; s < S1; ++s) {
        if (s + 1 < S1) {
            const int kt = (s + 1) * KC;
            const int jb = kt >> 9, ko = kt & (PD - 1);
            const int bsel = (s + 1) & 1;
            const int row = tid >> 2, kq = (tid & 3) * 4;
            cp16(AsA[bsel] + (row * 36 + kq) * 4, g_h + off[row * 4 + jb] + ko + kq);
            #pragma unroll
            for (int i = 0; i < 8; i++) {
                const int slot = i * 256 + tid;
                const int kk = slot >> 7, nq = (slot & 127) * 4;
                cp16(BsA[bsel] + (kk * 520 + nq) * 4, g_W1 + (size_t)(kt + kk) * N1 + nq);
            }
            CP_COMMIT();
            CP_WAIT(1);
        } else {
            CP_WAIT(0);
        }
        __syncthreads();

        const float* A  = Asb[s & 1];
        const float* Bt = Bsb[s & 1];
        #pragma unroll
        for (int ks = 0; ks < 2; ++ks) {
            const int k0 = ks * 8;
            uint32_t a[2][4];
            #pragma unroll
            for (int mf = 0; mf < 2; mf++) {
                const int R = wm * 32 + mf * 16;
                a[mf][0] = __float_as_uint(A[(R + lq) * 36 + k0 + lr]);
                a[mf][1] = __float_as_uint(A[(R + lq + 8) * 36 + k0 + lr]);
                a[mf][2] = __float_as_uint(A[(R + lq) * 36 + k0 + lr + 4]);
                a[mf][3] = __float_as_uint(A[(R + lq + 8) * 36 + k0 + lr + 4]);
            }
            #pragma unroll
            for (int nf = 0; nf < 16; nf++) {
                uint32_t b[2];
                const int C = wn * 128 + nf * 8 + lq;
                b[0] = __float_as_uint(Bt[(k0 + lr) * 520 + C]);
                b[1] = __float_as_uint(Bt[(k0 + lr + 4) * 520 + C]);
                mma_tf32(acc[0][nf], a[0], b);
                mma_tf32(acc[1][nf], a[1], b);
            }
        }
        __syncthreads();
    }

    // epilogue -> x1s (tf32-rounded)
    #pragma unroll
    for (int mf = 0; mf < 2; mf++) {
        const int Rb = wm * 32 + mf * 16;
        #pragma unroll
        for (int nf = 0; nf < 16; nf++) {
            const int col = wn * 128 + nf * 8 + 2 * lr;
            const float* c = acc[mf][nf];
            float2 v0, v1;
            v0.x = to_tf32(gelu_exact(c[0] + b1s[col]));
            v0.y = to_tf32(gelu_exact(c[1] + b1s[col + 1]));
            v1.x = to_tf32(gelu_exact(c[2] + b1s[col]));
            v1.y = to_tf32(gelu_exact(c[3] + b1s[col + 1]));
            *(float2*)&x1s[(Rb + lq) * 516 + col]     = v0;
            *(float2*)&x1s[(Rb + lq + 8) * 516 + col] = v1;
        }
    }
    __syncthreads();

    // ================= Phase 2: y = gelu(x1@W2+b2); out = sp(y.W3+b3) ========
    float acc2[2][8][4];
    #pragma unroll
    for (int mf = 0; mf < 2; mf++)
        #pragma unroll
        for (int nf = 0; nf < 8; nf++)
            #pragma unroll
            for (int q = 0; q < 4; q++) acc2[mf][nf][q] = 0.0f;

    const int S2 = K2 / KC;   // 32
    {
        #pragma unroll
        for (int i = 0; i < 4; i++) {
            const int slot = i * 256 + tid;
            const int kk = slot >> 6, nq = (slot & 63) * 4;
            cp16(BsA[0] + (kk * 264 + nq) * 4, g_W2 + (size_t)kk * N2 + nq);
        }
        CP_COMMIT();
    }

    for (int s = 0; s < S2; ++s) {
        if (s + 1 < S2) {
            const int kt = (s + 1) * KC;
            const int bsel = (s + 1) & 1;
            #pragma unroll
            for (int i = 0; i < 4; i++) {
                const int slot = i * 256 + tid;
                const int kk = slot >> 6, nq = (slot & 63) * 4;
                cp16(BsA[bsel] + (kk * 264 + nq) * 4, g_W2 + (size_t)(kt + kk) * N2 + nq);
            }
            CP_COMMIT();
            CP_WAIT(1);
        } else {
            CP_WAIT(0);
        }
        __syncthreads();

        const float* Bt = Bsb[s & 1];
        const int kbase = s * KC;
        #pragma unroll
        for (int ks = 0; ks < 2; ++ks) {
            const int k0 = ks * 8;
            uint32_t a[2][4];
            #pragma unroll
            for (int mf = 0; mf < 2; mf++) {
                const int R = wm * 32 + mf * 16;
                a[mf][0] = __float_as_uint(x1s[(R + lq) * 516 + kbase + k0 + lr]);
                a[mf][1] = __float_as_uint(x1s[(R + lq + 8) * 516 + kbase + k0 + lr]);
                a[mf][2] = __float_as_uint(x1s[(R + lq) * 516 + kbase + k0 + lr + 4]);
                a[mf][3] = __float_as_uint(x1s[(R + lq + 8) * 516 + kbase + k0 + lr + 4]);
            }
            #pragma unroll
            for (int nf = 0; nf < 8; nf++) {
                uint32_t b[2];
                const int C = wn * 64 + nf * 8 + lq;
                b[0] = __float_as_uint(Bt[(k0 + lr) * 264 + C]);
                b[1] = __float_as_uint(Bt[(k0 + lr + 4) * 264 + C]);
                mma_tf32(acc2[0][nf], a[0], b);
                mma_tf32(acc2[1][nf], a[1], b);
            }
        }
        __syncthreads();
    }

    // fused epilogue: gelu(+b2) . W3 -> quad-shuffle reduce -> softplus
    const float b3v = b3[0];
    #pragma unroll
    for (int mf = 0; mf < 2; mf++) {
        float p0 = 0.0f, p1 = 0.0f;
        #pragma unroll
        for (int nf = 0; nf < 8; nf++) {
            const int col = wn * 64 + nf * 8 + 2 * lr;
            const float* c = acc2[mf][nf];
            p0 = fmaf(gelu_exact(c[0] + b2s[col]),     w3s[col],     p0);
            p0 = fmaf(gelu_exact(c[1] + b2s[col + 1]), w3s[col + 1], p0);
            p1 = fmaf(gelu_exact(c[2] + b2s[col]),     w3s[col],     p1);
            p1 = fmaf(gelu_exact(c[3] + b2s[col + 1]), w3s[col + 1], p1);
        }
        p0 += __shfl_xor_sync(0xffffffffu, p0, 1);
        p0 += __shfl_xor_sync(0xffffffffu, p0, 2);
        p1 += __shfl_xor_sync(0xffffffffu, p1, 1);
        p1 += __shfl_xor_sync(0xffffffffu, p1, 2);
        if (lr == 0) {
            const int r0 = wm * 32 + mf * 16 + lq;
            red[r0 * 4 + wn]       = p0;
            red[(r0 + 8) * 4 + wn] = p1;
        }
    }
    __syncthreads();

    if (tid < MTILE) {
        const float ssum = red[tid * 4] + red[tid * 4 + 1] + red[tid * 4 + 2] + red[tid * 4 + 3];
        out[row0 + tid] = softplus_stable(ssum + b3v);
    }
}

extern "C" void kernel_launch(void* const* d_in, const int* in_sizes, int n_in,
                              void* d_out, int out_size)
{
    const float* h   = (const float*)d_in[0];
    const void*  idx = (const void*)d_in[1];
    const float* W1  = (const float*)d_in[2];
    const float* b1  = (const float*)d_in[3];
    const float* W2  = (const float*)d_in[4];
    const float* b2  = (const float*)d_in[5];
    const float* W3  = (const float*)d_in[6];
    const float* b3  = (const float*)d_in[7];
    float*       out = (float*)d_out;

    void *ph, *pw1, *pw2;
    cudaGetSymbolAddress(&ph,  g_h);
    cudaGetSymbolAddress(&pw1, g_W1);
    cudaGetSymbolAddress(&pw2, g_W2);

    cvt_tf32_kernel<<<1024, 256>>>((float*)ph,  h,  PB * PN * PD / 4);
    cvt_tf32_kernel<<<512,  256>>>((float*)pw1, W1, K1 * N1 / 4);
    cvt_tf32_kernel<<<128,  256>>>((float*)pw2, W2, K2 * N2 / 4);

    cudaFuncSetAttribute(swap_scoring_mma,
                         cudaFuncAttributeMaxDynamicSharedMemorySize, SMEM_BYTES);
    swap_scoring_mma<<<NROWS / MTILE, 256, SMEM_BYTES>>>(
        h, idx, b1, b2, W3, b3, out);
}

// round 6
// speedup vs baseline: 4.4933x; 1.0837x over previous
#include <cuda_runtime.h>
#include <cstdint>

// Problem: B=8, N=2048, D=512, S=4096
#define PB 8
#define PN 2048
#define PD 512
#define PS 4096
#define NROWS 32768
#define K1 2048
#define N1 512
#define K2 512
#define N2 256

#define MTILE 64
#define KC 16

// ---- tf32-rounded copies (device scratch) ----
__device__ float g_h[PB * PN * PD];     // 33.5 MB
__device__ float g_W1[K1 * N1];         // 4 MB
__device__ float g_W2[K2 * N2];         // 0.5 MB

// ---- smem layout (floats) ----
#define FX1   0                          // x1s [64][516]
#define FAS0  33024                      // A tile buf0 [64][36]
#define FAS1  35328
#define FBS0  37632                      // B tile buf0 [16][520]
#define FBS1  45952
#define FB1S  54272                      // b1 [512]
#define FB2S  54784                      // b2 [256]
#define FW3S  55040                      // W3 [256]
#define FRED  55296                      // red [64][8]
#define FOFF  55808                      // off [64][4] ints
#define FMODE 56064
#define SMEM_FLOATS 56068
#define SMEM_BYTES (SMEM_FLOATS * 4)

__device__ __forceinline__ float to_tf32(float x) {
    uint32_t u;
    asm("cvt.rna.tf32.f32 %0, %1;" : "=r"(u) : "f"(x));
    return __uint_as_float(u);
}
__device__ __forceinline__ float gelu_exact(float x) {
    return 0.5f * x * (1.0f + erff(x * 0.70710678118654752440f));
}
__device__ __forceinline__ float softplus_stable(float x) {
    return fmaxf(x, 0.0f) + log1pf(expf(-fabsf(x)));
}
__device__ __forceinline__ uint32_t smem_u32(const void* p) {
    uint32_t a;
    asm("{ .reg .u64 t; cvta.to.shared.u64 t, %1; cvt.u32.u64 %0, t; }" : "=r"(a) : "l"(p));
    return a;
}
__device__ __forceinline__ void cp16(uint32_t dst, const void* src) {
    asm volatile("cp.async.cg.shared.global [%0], [%1], 16;" :: "r"(dst), "l"(src));
}
#define CP_COMMIT() asm volatile("cp.async.commit_group;" ::: "memory")
#define CP_WAIT(n)  asm volatile("cp.async.wait_group %0;" :: "n"(n) : "memory")

__device__ __forceinline__ void mma_tf32(float* d, const uint32_t* a, const uint32_t* b) {
    asm volatile(
        "mma.sync.aligned.m16n8k8.row.col.f32.tf32.tf32.f32 "
        "{%0,%1,%2,%3}, {%4,%5,%6,%7}, {%8,%9}, {%0,%1,%2,%3};"
        : "+f"(d[0]), "+f"(d[1]), "+f"(d[2]), "+f"(d[3])
        : "r"(a[0]), "r"(a[1]), "r"(a[2]), "r"(a[3]), "r"(b[0]), "r"(b[1]));
}

// ---- prepass: round arrays to tf32 ----
__global__ void cvt_tf32_kernel(float* __restrict__ dst, const float* __restrict__ src, int n4) {
    for (int i = blockIdx.x * blockDim.x + threadIdx.x; i < n4; i += gridDim.x * blockDim.x) {
        float4 v = ((const float4*)src)[i];
        v.x = to_tf32(v.x); v.y = to_tf32(v.y); v.z = to_tf32(v.z); v.w = to_tf32(v.w);
        ((float4*)dst)[i] = v;
    }
}

// ============================================================================
__global__ void __launch_bounds__(512, 1)
swap_scoring_mma(const void* __restrict__ indices_raw,
                 const float* __restrict__ b1,
                 const float* __restrict__ b2,
                 const float* __restrict__ W3,
                 const float* __restrict__ b3,
                 float* __restrict__ out)
{
    extern __shared__ float sm[];
    float* x1s = sm + FX1;
    float* Asb[2] = { sm + FAS0, sm + FAS1 };
    float* Bsb[2] = { sm + FBS0, sm + FBS1 };
    float* b1s = sm + FB1S;
    float* b2s = sm + FB2S;
    float* w3s = sm + FW3S;
    float* red = sm + FRED;
    int*   off = (int*)(sm + FOFF);

    const uint32_t sb = smem_u32(sm);
    const uint32_t AsA[2] = { sb + FAS0 * 4, sb + FAS1 * 4 };
    const uint32_t BsA[2] = { sb + FBS0 * 4, sb + FBS1 * 4 };

    const int tid  = threadIdx.x;
    const int lane = tid & 31;
    const int wid  = tid >> 5;       // 0..15
    const int lq   = lane >> 2;      // 0..7
    const int lr   = lane & 3;       // 0..3
    const int wm   = wid >> 3;       // 0..1  (32-row slab)
    const int wn   = wid & 7;        // 0..7

    const int row0 = blockIdx.x * MTILE;
    const int bb   = row0 / PS;
    const int s0   = row0 % PS;

    // dtype detection (int64-LE => all odd 32-bit words zero; proven in R3)
    if (tid == 0) {
        const int* p32 = (const int*)indices_raw;
        int is64 = 1;
        #pragma unroll
        for (int t = 0; t < 32; t++)
            if (p32[2 * t + 1] != 0) { is64 = 0; break; }
        *(int*)(sm + FMODE) = is64;
    }
    if (tid < 512) b1s[tid] = b1[tid];
    if (tid < 256) { b2s[tid] = b2[tid]; w3s[tid] = W3[tid]; }
    __syncthreads();

    const int is64 = *(const int*)(sm + FMODE);
    if (tid < MTILE * 4) {
        const int m = tid >> 2, j = tid & 3;
        const long long e = ((long long)(bb * PS + s0 + m)) * 4 + j;
        int idx;
        if (is64) idx = (int)((const long long*)indices_raw)[e];
        else      idx = ((const int*)indices_raw)[e];
        off[m * 4 + j] = (bb * PN + (idx & (PN - 1))) * PD;
    }
    __syncthreads();

    // ======================= Phase 1: x1 = gelu(A@W1+b1) =====================
    // Warp tile 32(m) x 64(n): acc[2 mf][8 nf][4]
    float acc[2][8][4];
    #pragma unroll
    for (int mf = 0; mf < 2; mf++)
        #pragma unroll
        for (int nf = 0; nf < 8; nf++)
            #pragma unroll
            for (int q = 0; q < 4; q++) acc[mf][nf][q] = 0.0f;

    const int S1 = K1 / KC;   // 128

    // stage 0
    {
        if (tid < 256) {
            const int row = tid >> 2, kq = (tid & 3) * 4;
            cp16(AsA[0] + (row * 36 + kq) * 4, g_h + off[row * 4 + 0] + 0 + kq);
        }
        #pragma unroll
        for (int i = 0; i < 4; i++) {
            const int slot = i * 512 + tid;
            const int kk = slot >> 7, nq = (slot & 127) * 4;
            cp16(BsA[0] + (kk * 520 + nq) * 4, g_W1 + (size_t)kk * N1 + nq);
        }
        CP_COMMIT();
    }

    for (int s = 0; s < S1; ++s) {
        if (s + 1 < S1) {
            const int kt = (s + 1) * KC;
            const int jb = kt >> 9, ko = kt & (PD - 1);
            const int bsel = (s + 1) & 1;
            if (tid < 256) {
                const int row = tid >> 2, kq = (tid & 3) * 4;
                cp16(AsA[bsel] + (row * 36 + kq) * 4, g_h + off[row * 4 + jb] + ko + kq);
            }
            #pragma unroll
            for (int i = 0; i < 4; i++) {
                const int slot = i * 512 + tid;
                const int kk = slot >> 7, nq = (slot & 127) * 4;
                cp16(BsA[bsel] + (kk * 520 + nq) * 4, g_W1 + (size_t)(kt + kk) * N1 + nq);
            }
            CP_COMMIT();
            CP_WAIT(1);
        } else {
            CP_WAIT(0);
        }
        __syncthreads();

        const float* A  = Asb[s & 1];
        const float* Bt = Bsb[s & 1];
        #pragma unroll
        for (int ks = 0; ks < 2; ++ks) {
            const int k0 = ks * 8;
            uint32_t a[2][4];
            #pragma unroll
            for (int mf = 0; mf < 2; mf++) {
                const int R = wm * 32 + mf * 16;
                a[mf][0] = __float_as_uint(A[(R + lq) * 36 + k0 + lr]);
                a[mf][1] = __float_as_uint(A[(R + lq + 8) * 36 + k0 + lr]);
                a[mf][2] = __float_as_uint(A[(R + lq) * 36 + k0 + lr + 4]);
                a[mf][3] = __float_as_uint(A[(R + lq + 8) * 36 + k0 + lr + 4]);
            }
            #pragma unroll
            for (int nf = 0; nf < 8; nf++) {
                uint32_t b[2];
                const int C = wn * 64 + nf * 8 + lq;
                b[0] = __float_as_uint(Bt[(k0 + lr) * 520 + C]);
                b[1] = __float_as_uint(Bt[(k0 + lr + 4) * 520 + C]);
                mma_tf32(acc[0][nf], a[0], b);
                mma_tf32(acc[1][nf], a[1], b);
            }
        }
        __syncthreads();
    }

    // epilogue -> x1s (tf32-rounded)
    #pragma unroll
    for (int mf = 0; mf < 2; mf++) {
        const int Rb = wm * 32 + mf * 16;
        #pragma unroll
        for (int nf = 0; nf < 8; nf++) {
            const int col = wn * 64 + nf * 8 + 2 * lr;
            const float* c = acc[mf][nf];
            float2 v0, v1;
            v0.x = to_tf32(gelu_exact(c[0] + b1s[col]));
            v0.y = to_tf32(gelu_exact(c[1] + b1s[col + 1]));
            v1.x = to_tf32(gelu_exact(c[2] + b1s[col]));
            v1.y = to_tf32(gelu_exact(c[3] + b1s[col + 1]));
            *(float2*)&x1s[(Rb + lq) * 516 + col]     = v0;
            *(float2*)&x1s[(Rb + lq + 8) * 516 + col] = v1;
        }
    }
    __syncthreads();

    // ================= Phase 2: y = gelu(x1@W2+b2); out = sp(y.W3+b3) ========
    // Warp tile 32(m) x 32(n): acc2[2][4][4]
    float acc2[2][4][4];
    #pragma unroll
    for (int mf = 0; mf < 2; mf++)
        #pragma unroll
        for (int nf = 0; nf < 4; nf++)
            #pragma unroll
            for (int q = 0; q < 4; q++) acc2[mf][nf][q] = 0.0f;

    const int S2 = K2 / KC;   // 32
    {
        #pragma unroll
        for (int i = 0; i < 2; i++) {
            const int slot = i * 512 + tid;
            const int kk = slot >> 6, nq = (slot & 63) * 4;
            cp16(BsA[0] + (kk * 264 + nq) * 4, g_W2 + (size_t)kk * N2 + nq);
        }
        CP_COMMIT();
    }

    for (int s = 0; s < S2; ++s) {
        if (s + 1 < S2) {
            const int kt = (s + 1) * KC;
            const int bsel = (s + 1) & 1;
            #pragma unroll
            for (int i = 0; i < 2; i++) {
                const int slot = i * 512 + tid;
                const int kk = slot >> 6, nq = (slot & 63) * 4;
                cp16(BsA[bsel] + (kk * 264 + nq) * 4, g_W2 + (size_t)(kt + kk) * N2 + nq);
            }
            CP_COMMIT();
            CP_WAIT(1);
        } else {
            CP_WAIT(0);
        }
        __syncthreads();

        const float* Bt = Bsb[s & 1];
        const int kbase = s * KC;
        #pragma unroll
        for (int ks = 0; ks < 2; ++ks) {
            const int k0 = ks * 8;
            uint32_t a[2][4];
            #pragma unroll
            for (int mf = 0; mf < 2; mf++) {
                const int R = wm * 32 + mf * 16;
                a[mf][0] = __float_as_uint(x1s[(R + lq) * 516 + kbase + k0 + lr]);
                a[mf][1] = __float_as_uint(x1s[(R + lq + 8) * 516 + kbase + k0 + lr]);
                a[mf][2] = __float_as_uint(x1s[(R + lq) * 516 + kbase + k0 + lr + 4]);
                a[mf][3] = __float_as_uint(x1s[(R + lq + 8) * 516 + kbase + k0 + lr + 4]);
            }
            #pragma unroll
            for (int nf = 0; nf < 4; nf++) {
                uint32_t b[2];
                const int C = wn * 32 + nf * 8 + lq;
                b[0] = __float_as_uint(Bt[(k0 + lr) * 264 + C]);
                b[1] = __float_as_uint(Bt[(k0 + lr + 4) * 264 + C]);
                mma_tf32(acc2[0][nf], a[0], b);
                mma_tf32(acc2[1][nf], a[1], b);
            }
        }
        __syncthreads();
    }

    // fused epilogue: gelu(+b2) . W3 -> quad-shuffle reduce -> softplus
    const float b3v = b3[0];
    #pragma unroll
    for (int mf = 0; mf < 2; mf++) {
        float p0 = 0.0f, p1 = 0.0f;
        #pragma unroll
        for (int nf = 0; nf < 4; nf++) {
            const int col = wn * 32 + nf * 8 + 2 * lr;
            const float* c = acc2[mf][nf];
            p0 = fmaf(gelu_exact(c[0] + b2s[col]),     w3s[col],     p0);
            p0 = fmaf(gelu_exact(c[1] + b2s[col + 1]), w3s[col + 1], p0);
            p1 = fmaf(gelu_exact(c[2] + b2s[col]),     w3s[col],     p1);
            p1 = fmaf(gelu_exact(c[3] + b2s[col + 1]), w3s[col + 1], p1);
        }
        p0 += __shfl_xor_sync(0xffffffffu, p0, 1);
        p0 += __shfl_xor_sync(0xffffffffu, p0, 2);
        p1 += __shfl_xor_sync(0xffffffffu, p1, 1);
        p1 += __shfl_xor_sync(0xffffffffu, p1, 2);
        if (lr == 0) {
            const int r0 = wm * 32 + mf * 16 + lq;
            red[r0 * 8 + wn]       = p0;
            red[(r0 + 8) * 8 + wn] = p1;
        }
    }
    __syncthreads();

    if (tid < MTILE) {
        const float* rr = &red[tid * 8];
        float ssum = rr[0] + rr[1] + rr[2] + rr[3] + rr[4] + rr[5] + rr[6] + rr[7];
        out[row0 + tid] = softplus_stable(ssum + b3v);
    }
}

extern "C" void kernel_launch(void* const* d_in, const int* in_sizes, int n_in,
                              void* d_out, int out_size)
{
    const float* h   = (const float*)d_in[0];
    const void*  idx = (const void*)d_in[1];
    const float* W1  = (const float*)d_in[2];
    const float* b1  = (const float*)d_in[3];
    const float* W2  = (const float*)d_in[4];
    const float* b2  = (const float*)d_in[5];
    const float* W3  = (const float*)d_in[6];
    const float* b3  = (const float*)d_in[7];
    float*       out = (float*)d_out;

    void *ph, *pw1, *pw2;
    cudaGetSymbolAddress(&ph,  g_h);
    cudaGetSymbolAddress(&pw1, g_W1);
    cudaGetSymbolAddress(&pw2, g_W2);

    cvt_tf32_kernel<<<1024, 256>>>((float*)ph,  h,  PB * PN * PD / 4);
    cvt_tf32_kernel<<<512,  256>>>((float*)pw1, W1, K1 * N1 / 4);
    cvt_tf32_kernel<<<128,  256>>>((float*)pw2, W2, K2 * N2 / 4);

    cudaFuncSetAttribute(swap_scoring_mma,
                         cudaFuncAttributeMaxDynamicSharedMemorySize, SMEM_BYTES);
    swap_scoring_mma<<<NROWS / MTILE, 512, SMEM_BYTES>>>(
        idx, b1, b2, W3, b3, out);
}

// round 7
// speedup vs baseline: 8.2463x; 1.8353x over previous
#include <cuda_runtime.h>
#include <cuda_fp16.h>
#include <cstdint>

#define PB 8
#define PN 2048
#define PD 512
#define PS 4096
#define NROWS 32768
#define K1 2048
#define N1 512
#define K2 512
#define N2 256
#define MTILE 64
#define KC 32
#define NSTG1 (K1 / KC)   // 64
#define NSTG2 (K2 / KC)   // 16

// ---- device scratch: fp16 copies (h same layout; W1/W2 transposed to [n][k]) ----
__device__ __half g_h[PB * PN * PD];
__device__ __half g_W1t[N1 * K1];
__device__ __half g_W2t[N2 * K2];

// ---- smem layout in 32-bit words ----
#define WX1   0                      // x1: 64 rows x 256 kp-words = 16384
#define WA0   16384                  // A bufs: 3 x 1024
#define WB0   (16384 + 3072)         // B bufs: 3 x 8192
#define WB1S  (WB0 + 24576)          // b1: 512 floats
#define WB2S  (WB1S + 512)           // b2: 256
#define WW3S  (WB2S + 256)           // W3: 256
#define WRED  (WW3S + 256)           // red: 512
#define WOFF  (WRED + 512)           // off: 256 ints
#define WMODE (WOFF + 256)
#define SMEM_WORDS (WMODE + 4)
#define SMEM_BYTES (SMEM_WORDS * 4)

__device__ __forceinline__ float gelu_exact(float x) {
    return 0.5f * x * (1.0f + erff(x * 0.70710678118654752440f));
}
__device__ __forceinline__ float softplus_stable(float x) {
    return fmaxf(x, 0.0f) + log1pf(expf(-fabsf(x)));
}
__device__ __forceinline__ uint32_t smem_u32(const void* p) {
    uint32_t a;
    asm("{ .reg .u64 t; cvta.to.shared.u64 t, %1; cvt.u32.u64 %0, t; }" : "=r"(a) : "l"(p));
    return a;
}
__device__ __forceinline__ void cp16(uint32_t dst, const void* src) {
    asm volatile("cp.async.cg.shared.global [%0], [%1], 16;" :: "r"(dst), "l"(src));
}
#define CP_COMMIT() asm volatile("cp.async.commit_group;" ::: "memory")
#define CP_WAIT(n)  asm volatile("cp.async.wait_group %0;" :: "n"(n) : "memory")

__device__ __forceinline__ void mma_f16(float* d, const uint32_t* a, const uint32_t* b) {
    asm volatile(
        "mma.sync.aligned.m16n8k16.row.col.f32.f16.f16.f32 "
        "{%0,%1,%2,%3}, {%4,%5,%6,%7}, {%8,%9}, {%0,%1,%2,%3};"
        : "+f"(d[0]), "+f"(d[1]), "+f"(d[2]), "+f"(d[3])
        : "r"(a[0]), "r"(a[1]), "r"(a[2]), "r"(a[3]), "r"(b[0]), "r"(b[1]));
}

// ---- swizzled word addresses (derived conflict-free; see analysis) ----
// A tile: 64 rows x 16 kp-words per stage
__device__ __forceinline__ int awd(int r, int kp) {
    return r * 16 + ((((kp >> 2) ^ ((r >> 1) & 3)) << 2) | (kp & 3));
}
// B tile: n rows x 16 kp-words per stage
__device__ __forceinline__ int bwd(int n, int kp) {
    return n * 16 + ((((kp >> 2) ^ ((n >> 1) & 3)) << 2) | (kp & 3));
}
// x1: 64 rows x 256 kp-words, word-level XOR swizzle
__device__ __forceinline__ int xwd(int r, int kp) {
    return r * 256 + (kp ^ ((r & 7) << 2));
}

// ---- prepass kernels ----
__global__ void cvt_h_kernel(__half* __restrict__ dst, const float* __restrict__ src, int n4) {
    for (int i = blockIdx.x * blockDim.x + threadIdx.x; i < n4; i += gridDim.x * blockDim.x) {
        const float4 v = ((const float4*)src)[i];
        __half2 lo = __floats2half2_rn(v.x, v.y);
        __half2 hi = __floats2half2_rn(v.z, v.w);
        ((__half2*)dst)[2 * i]     = lo;
        ((__half2*)dst)[2 * i + 1] = hi;
    }
}

__global__ void transpose_half_kernel(__half* __restrict__ dst, const float* __restrict__ src,
                                      int K, int N) {
    __shared__ __half t[32][33];
    const int k0 = blockIdx.y * 32, n0 = blockIdx.x * 32;
    const int tx = threadIdx.x, ty = threadIdx.y;
    #pragma unroll
    for (int i = 0; i < 32; i += 8)
        t[ty + i][tx] = __float2half_rn(src[(size_t)(k0 + ty + i) * N + n0 + tx]);
    __syncthreads();
    #pragma unroll
    for (int i = 0; i < 32; i += 8)
        dst[(size_t)(n0 + ty + i) * K + k0 + tx] = t[tx][ty + i];
}

// ============================================================================
__global__ void __launch_bounds__(512, 1)
swap_scoring_f16(const void* __restrict__ indices_raw,
                 const float* __restrict__ b1,
                 const float* __restrict__ b2,
                 const float* __restrict__ W3,
                 const float* __restrict__ b3,
                 float* __restrict__ out)
{
    extern __shared__ uint32_t smw[];
    float* b1s = (float*)(smw + WB1S);
    float* b2s = (float*)(smw + WB2S);
    float* w3s = (float*)(smw + WW3S);
    float* red = (float*)(smw + WRED);
    int*   off = (int*)(smw + WOFF);

    const uint32_t sb = smem_u32(smw);

    const int tid  = threadIdx.x;
    const int lane = tid & 31;
    const int wid  = tid >> 5;       // 0..15
    const int lq   = lane >> 2;      // 0..7
    const int lr   = lane & 3;       // 0..3
    const int wm   = wid >> 3;       // 0..1
    const int wn   = wid & 7;        // 0..7

    const int row0 = blockIdx.x * MTILE;
    const int bb   = row0 / PS;
    const int s0   = row0 % PS;

    if (tid == 0) {
        const int* p32 = (const int*)indices_raw;
        int is64 = 1;
        #pragma unroll
        for (int t = 0; t < 32; t++)
            if (p32[2 * t + 1] != 0) { is64 = 0; break; }
        *(int*)(smw + WMODE) = is64;
    }
    b1s[tid] = b1[tid];
    if (tid < 256) { b2s[tid] = b2[tid]; w3s[tid] = W3[tid]; }
    __syncthreads();

    const int is64 = *(const int*)(smw + WMODE);
    if (tid < MTILE * 4) {
        const int m = tid >> 2, j = tid & 3;
        const long long e = ((long long)(bb * PS + s0 + m)) * 4 + j;
        int idx;
        if (is64) idx = (int)((const long long*)indices_raw)[e];
        else      idx = ((const int*)indices_raw)[e];
        off[m * 4 + j] = (bb * PN + (idx & (PN - 1))) * PD;
    }
    __syncthreads();

    // stage buffer SMEM byte addresses
    uint32_t AsA[3], BsA[3];
    #pragma unroll
    for (int i = 0; i < 3; i++) {
        AsA[i] = sb + (WA0 + i * 1024) * 4;
        BsA[i] = sb + (WB0 + i * 8192) * 4;
    }

    // ---- pipeline issue helpers ----
    auto issueA = [&](int buf, int kt) {
        if (tid < 256) {
            const int row = tid >> 2, g = tid & 3;
            const int jb = kt >> 9, ko = kt & (PD - 1);
            cp16(AsA[buf] + (row * 16 + ((g ^ ((row >> 1) & 3)) << 2)) * 4,
                 g_h + off[row * 4 + jb] + ko + g * 8);
        }
    };
    auto issueB1 = [&](int buf, int kt) {
        #pragma unroll
        for (int p = 0; p < 4; p++) {
            const int n = p * 128 + (tid >> 2), g = tid & 3;
            cp16(BsA[buf] + (n * 16 + ((g ^ ((n >> 1) & 3)) << 2)) * 4,
                 g_W1t + (size_t)n * K1 + kt + g * 8);
        }
    };
    auto issueB2 = [&](int buf, int kt) {
        #pragma unroll
        for (int p = 0; p < 2; p++) {
            const int n = p * 128 + (tid >> 2), g = tid & 3;
            cp16(BsA[buf] + (n * 16 + ((g ^ ((n >> 1) & 3)) << 2)) * 4,
                 g_W2t + (size_t)n * K2 + kt + g * 8);
        }
    };

    // ======================= Phase 1: x1 = gelu(A@W1+b1) =====================
    float acc[2][8][4];
    #pragma unroll
    for (int mf = 0; mf < 2; mf++)
        #pragma unroll
        for (int nf = 0; nf < 8; nf++)
            #pragma unroll
            for (int q = 0; q < 4; q++) acc[mf][nf][q] = 0.0f;

    issueA(0, 0);  issueB1(0, 0);  CP_COMMIT();
    issueA(1, KC); issueB1(1, KC); CP_COMMIT();

    for (int s = 0; s < NSTG1; ++s) {
        CP_WAIT(1);
        __syncthreads();
        if (s + 2 < NSTG1) { issueA((s + 2) % 3, (s + 2) * KC); issueB1((s + 2) % 3, (s + 2) * KC); }
        CP_COMMIT();

        const uint32_t* A = smw + WA0 + (s % 3) * 1024;
        const uint32_t* B = smw + WB0 + (s % 3) * 8192;
        #pragma unroll
        for (int ks = 0; ks < 2; ++ks) {
            const int kp0 = ks * 8;
            uint32_t a[2][4];
            #pragma unroll
            for (int mf = 0; mf < 2; mf++) {
                const int R = wm * 32 + mf * 16;
                a[mf][0] = A[awd(R + lq,     kp0 + lr)];
                a[mf][1] = A[awd(R + lq + 8, kp0 + lr)];
                a[mf][2] = A[awd(R + lq,     kp0 + 4 + lr)];
                a[mf][3] = A[awd(R + lq + 8, kp0 + 4 + lr)];
            }
            uint32_t bf[8][2];
            #pragma unroll
            for (int nf = 0; nf < 8; nf++) {
                const int C = wn * 64 + nf * 8 + lq;
                bf[nf][0] = B[bwd(C, kp0 + lr)];
                bf[nf][1] = B[bwd(C, kp0 + 4 + lr)];
            }
            #pragma unroll
            for (int nf = 0; nf < 8; nf++) {
                mma_f16(acc[0][nf], a[0], bf[nf]);
                mma_f16(acc[1][nf], a[1], bf[nf]);
            }
        }
    }
    __syncthreads();

    // epilogue 1: gelu(+b1) -> half pairs into swizzled x1
    #pragma unroll
    for (int mf = 0; mf < 2; mf++) {
        const int r0 = wm * 32 + mf * 16 + lq;
        #pragma unroll
        for (int nf = 0; nf < 8; nf++) {
            const int col = wn * 64 + nf * 8 + 2 * lr;
            const int kp  = wn * 32 + nf * 4 + lr;
            const float* c = acc[mf][nf];
            __half2 lo = __floats2half2_rn(gelu_exact(c[0] + b1s[col]),
                                           gelu_exact(c[1] + b1s[col + 1]));
            __half2 hi = __floats2half2_rn(gelu_exact(c[2] + b1s[col]),
                                           gelu_exact(c[3] + b1s[col + 1]));
            smw[WX1 + xwd(r0, kp)]     = *(const uint32_t*)&lo;
            smw[WX1 + xwd(r0 + 8, kp)] = *(const uint32_t*)&hi;
        }
    }
    __syncthreads();

    // ================= Phase 2: y = gelu(x1@W2+b2); out = sp(y.W3+b3) ========
    float acc2[2][4][4];
    #pragma unroll
    for (int mf = 0; mf < 2; mf++)
        #pragma unroll
        for (int nf = 0; nf < 4; nf++)
            #pragma unroll
            for (int q = 0; q < 4; q++) acc2[mf][nf][q] = 0.0f;

    issueB2(0, 0);  CP_COMMIT();
    issueB2(1, KC); CP_COMMIT();

    const uint32_t* X = smw + WX1;
    for (int s = 0; s < NSTG2; ++s) {
        CP_WAIT(1);
        __syncthreads();
        if (s + 2 < NSTG2) issueB2((s + 2) % 3, (s + 2) * KC);
        CP_COMMIT();

        const uint32_t* B = smw + WB0 + (s % 3) * 8192;
        const int ktp = s * (KC / 2);     // kp base of this stage
        #pragma unroll
        for (int ks = 0; ks < 2; ++ks) {
            const int kpb = ktp + ks * 8;
            uint32_t a[2][4];
            #pragma unroll
            for (int mf = 0; mf < 2; mf++) {
                const int R = wm * 32 + mf * 16;
                a[mf][0] = X[xwd(R + lq,     kpb + lr)];
                a[mf][1] = X[xwd(R + lq + 8, kpb + lr)];
                a[mf][2] = X[xwd(R + lq,     kpb + 4 + lr)];
                a[mf][3] = X[xwd(R + lq + 8, kpb + 4 + lr)];
            }
            uint32_t bf[4][2];
            #pragma unroll
            for (int nf = 0; nf < 4; nf++) {
                const int C = wn * 32 + nf * 8 + lq;
                bf[nf][0] = B[bwd(C, ks * 8 + lr)];
                bf[nf][1] = B[bwd(C, ks * 8 + 4 + lr)];
            }
            #pragma unroll
            for (int nf = 0; nf < 4; nf++) {
                mma_f16(acc2[0][nf], a[0], bf[nf]);
                mma_f16(acc2[1][nf], a[1], bf[nf]);
            }
        }
    }

    // fused epilogue: gelu(+b2) . W3 -> quad-shuffle reduce -> softplus
    const float b3v = b3[0];
    #pragma unroll
    for (int mf = 0; mf < 2; mf++) {
        float p0 = 0.0f, p1 = 0.0f;
        #pragma unroll
        for (int nf = 0; nf < 4; nf++) {
            const int col = wn * 32 + nf * 8 + 2 * lr;
            const float* c = acc2[mf][nf];
            p0 = fmaf(gelu_exact(c[0] + b2s[col]),     w3s[col],     p0);
            p0 = fmaf(gelu_exact(c[1] + b2s[col + 1]), w3s[col + 1], p0);
            p1 = fmaf(gelu_exact(c[2] + b2s[col]),     w3s[col],     p1);
            p1 = fmaf(gelu_exact(c[3] + b2s[col + 1]), w3s[col + 1], p1);
        }
        p0 += __shfl_xor_sync(0xffffffffu, p0, 1);
        p0 += __shfl_xor_sync(0xffffffffu, p0, 2);
        p1 += __shfl_xor_sync(0xffffffffu, p1, 1);
        p1 += __shfl_xor_sync(0xffffffffu, p1, 2);
        if (lr == 0) {
            const int r0 = wm * 32 + mf * 16 + lq;
            red[r0 * 8 + wn]       = p0;
            red[(r0 + 8) * 8 + wn] = p1;
        }
    }
    __syncthreads();

    if (tid < MTILE) {
        const float* rr = &red[tid * 8];
        const float ssum = rr[0] + rr[1] + rr[2] + rr[3] + rr[4] + rr[5] + rr[6] + rr[7];
        out[row0 + tid] = softplus_stable(ssum + b3v);
    }
}

extern "C" void kernel_launch(void* const* d_in, const int* in_sizes, int n_in,
                              void* d_out, int out_size)
{
    const float* h   = (const float*)d_in[0];
    const void*  idx = (const void*)d_in[1];
    const float* W1  = (const float*)d_in[2];
    const float* b1  = (const float*)d_in[3];
    const float* W2  = (const float*)d_in[4];
    const float* b2  = (const float*)d_in[5];
    const float* W3  = (const float*)d_in[6];
    const float* b3  = (const float*)d_in[7];
    float*       out = (float*)d_out;

    void *ph, *pw1, *pw2;
    cudaGetSymbolAddress(&ph,  g_h);
    cudaGetSymbolAddress(&pw1, g_W1t);
    cudaGetSymbolAddress(&pw2, g_W2t);

    cvt_h_kernel<<<2048, 256>>>((__half*)ph, h, PB * PN * PD / 4);
    transpose_half_kernel<<<dim3(N1 / 32, K1 / 32), dim3(32, 8)>>>((__half*)pw1, W1, K1, N1);
    transpose_half_kernel<<<dim3(N2 / 32, K2 / 32), dim3(32, 8)>>>((__half*)pw2, W2, K2, N2);

    cudaFuncSetAttribute(swap_scoring_f16,
                         cudaFuncAttributeMaxDynamicSharedMemorySize, SMEM_BYTES);
    swap_scoring_f16<<<NROWS / MTILE, 512, SMEM_BYTES>>>(
        idx, b1, b2, W3, b3, out);
}

// round 9
// speedup vs baseline: 11.0564x; 1.3408x over previous
#include <cuda_runtime.h>
#include <cuda_fp16.h>
#include <cstdint>

#define PB 8
#define PN 2048
#define PD 512
#define PS 4096
#define NROWS 32768
#define K1 2048
#define N1 512
#define K2 512
#define N2 256
#define MTILE 64
#define KC 32
#define NSTG1 (K1 / KC)   // 64
#define NSTG2 (K2 / KC)   // 16

// ---- device scratch: fp16 copies (h same layout; W1/W2 transposed to [n][k]) ----
__device__ __half g_h[PB * PN * PD];
__device__ __half g_W1t[N1 * K1];
__device__ __half g_W2t[N2 * K2];

// ---- smem layout in 32-bit words ----
#define WX1   0                      // x1: 64 rows x 256 kp-words = 16384
#define WA0   16384                  // A bufs: 3 x 1024
#define WB0   (16384 + 3072)         // B bufs: 3 x 8192
#define WB1S  (WB0 + 24576)          // b1: 512 floats
#define WB2S  (WB1S + 512)           // b2: 256
#define WW3S  (WB2S + 256)           // W3: 256
#define WRED  (WW3S + 256)           // red: 512
#define WOFF  (WRED + 512)           // off: 256 ints
#define WMODE (WOFF + 256)
#define SMEM_WORDS (WMODE + 4)
#define SMEM_BYTES (SMEM_WORDS * 4)

__device__ __forceinline__ float gelu_exact(float x) {
    return 0.5f * x * (1.0f + erff(x * 0.70710678118654752440f));
}
__device__ __forceinline__ float softplus_stable(float x) {
    return fmaxf(x, 0.0f) + log1pf(expf(-fabsf(x)));
}
__device__ __forceinline__ uint32_t smem_u32(const void* p) {
    uint32_t a;
    asm("{ .reg .u64 t; cvta.to.shared.u64 t, %1; cvt.u32.u64 %0, t; }" : "=r"(a) : "l"(p));
    return a;
}
__device__ __forceinline__ void cp16(uint32_t dst, const void* src) {
    asm volatile("cp.async.cg.shared.global [%0], [%1], 16;" :: "r"(dst), "l"(src));
}
#define CP_COMMIT() asm volatile("cp.async.commit_group;" ::: "memory")
#define CP_WAIT(n)  asm volatile("cp.async.wait_group %0;" :: "n"(n) : "memory")

__device__ __forceinline__ void mma_f16(float* d, const uint32_t* a, const uint32_t* b) {
    asm volatile(
        "mma.sync.aligned.m16n8k16.row.col.f32.f16.f16.f32 "
        "{%0,%1,%2,%3}, {%4,%5,%6,%7}, {%8,%9}, {%0,%1,%2,%3};"
        : "+f"(d[0]), "+f"(d[1]), "+f"(d[2]), "+f"(d[3])
        : "r"(a[0]), "r"(a[1]), "r"(a[2]), "r"(a[3]), "r"(b[0]), "r"(b[1]));
}
__device__ __forceinline__ void ldsm4(uint32_t* r, uint32_t addr) {
    asm volatile("ldmatrix.sync.aligned.m8n8.x4.shared.b16 {%0,%1,%2,%3}, [%4];"
        : "=r"(r[0]), "=r"(r[1]), "=r"(r[2]), "=r"(r[3]) : "r"(addr));
}

// word-address swizzles (granule g = 16B = 4 words = 8 halves)
__device__ __forceinline__ int awd_g(int r, int g) { return r * 16 + 4 * (g ^ ((r >> 1) & 3)); }
__device__ __forceinline__ int xwd_w(int r, int kp) { return r * 256 + (kp ^ ((r & 7) << 2)); }

// ---- prepass kernels ----
__global__ void cvt_h_kernel(__half* __restrict__ dst, const float* __restrict__ src, int n4) {
    for (int i = blockIdx.x * blockDim.x + threadIdx.x; i < n4; i += gridDim.x * blockDim.x) {
        const float4 v = ((const float4*)src)[i];
        __half2 lo = __floats2half2_rn(v.x, v.y);
        __half2 hi = __floats2half2_rn(v.z, v.w);
        ((__half2*)dst)[2 * i]     = lo;
        ((__half2*)dst)[2 * i + 1] = hi;
    }
}

__global__ void transpose_half_kernel(__half* __restrict__ dst, const float* __restrict__ src,
                                      int K, int N) {
    __shared__ __half t[32][33];
    const int k0 = blockIdx.y * 32, n0 = blockIdx.x * 32;
    const int tx = threadIdx.x, ty = threadIdx.y;
    #pragma unroll
    for (int i = 0; i < 32; i += 8)
        t[ty + i][tx] = __float2half_rn(src[(size_t)(k0 + ty + i) * N + n0 + tx]);
    __syncthreads();
    #pragma unroll
    for (int i = 0; i < 32; i += 8)
        dst[(size_t)(n0 + ty + i) * K + k0 + tx] = t[tx][ty + i];
}

// ============================================================================
__global__ void __launch_bounds__(512, 1)
swap_scoring_f16(const void* __restrict__ indices_raw,
                 const float* __restrict__ b1,
                 const float* __restrict__ b2,
                 const float* __restrict__ W3,
                 const float* __restrict__ b3,
                 float* __restrict__ out)
{
    extern __shared__ uint32_t smw[];
    float* b1s = (float*)(smw + WB1S);
    float* b2s = (float*)(smw + WB2S);
    float* w3s = (float*)(smw + WW3S);
    float* red = (float*)(smw + WRED);
    int*   off = (int*)(smw + WOFF);

    const uint32_t sb = smem_u32(smw);

    const int tid  = threadIdx.x;
    const int lane = tid & 31;
    const int wid  = tid >> 5;       // 0..15
    const int lq   = lane >> 2;      // 0..7
    const int lr   = lane & 3;       // 0..3
    const int wm   = wid >> 3;       // 0..1
    const int wn   = wid & 7;        // 0..7

    const int row0 = blockIdx.x * MTILE;
    const int bb   = row0 / PS;
    const int s0   = row0 % PS;

    if (tid == 0) {
        const int* p32 = (const int*)indices_raw;
        int is64 = 1;
        #pragma unroll
        for (int t = 0; t < 32; t++)
            if (p32[2 * t + 1] != 0) { is64 = 0; break; }
        *(int*)(smw + WMODE) = is64;
    }
    b1s[tid] = b1[tid];
    if (tid < 256) { b2s[tid] = b2[tid]; w3s[tid] = W3[tid]; }
    __syncthreads();

    const int is64 = *(const int*)(smw + WMODE);
    if (tid < MTILE * 4) {
        const int m = tid >> 2, j = tid & 3;
        const long long e = ((long long)(bb * PS + s0 + m)) * 4 + j;
        int idx;
        if (is64) idx = (int)((const long long*)indices_raw)[e];
        else      idx = ((const int*)indices_raw)[e];
        off[m * 4 + j] = (bb * PN + (idx & (PN - 1))) * PD;
    }
    __syncthreads();

    const uint32_t sbA = sb + WA0 * 4;
    const uint32_t sbB = sb + WB0 * 4;
    const uint32_t sbX = sb + WX1 * 4;

    // ---- precomputed ldmatrix lane offsets (byte offsets inside a buffer) ----
    // A / x1 (non-trans): lanes 0-15 -> rows R..R+15 at granule +0; lanes 16-31 same rows +1 granule
    const int arow = wm * 32 + (lane & 15);
    const int ghalf = lane >> 4;                      // 0/1 (k granule bit)
    const uint32_t aoff0 = (uint32_t)awd_g(arow, 0 + ghalf) * 4;
    const uint32_t aoff1 = (uint32_t)awd_g(arow, 2 + ghalf) * 4;
    // B (non-trans, n-major rows): n = C0 + ((l>>4)<<3) + (l&7); granule bit = (l>>3)&1
    // matrices: {n-oct0/g, n-oct0/g+1, n-oct1/g, n-oct1/g+1} -> bf[2p][0],bf[2p][1],bf[2p+1][0],bf[2p+1][1]
    const int bn0 = wn * 64 + ((lane >> 4) << 3) + (lane & 7);
    const int bg  = (lane >> 3) & 1;
    const uint32_t boff0 = (uint32_t)awd_g(bn0, 0 + bg) * 4;
    const uint32_t boff1 = (uint32_t)awd_g(bn0, 2 + bg) * 4;
    const int bn2 = wn * 32 + ((lane >> 4) << 3) + (lane & 7);
    const uint32_t b2off0 = (uint32_t)awd_g(bn2, 0 + bg) * 4;
    const uint32_t b2off1 = (uint32_t)awd_g(bn2, 2 + bg) * 4;

    // ---- pipeline issue helpers ----
    auto issueA = [&](int buf, int kt) {
        if (tid < 256) {
            const int row = tid >> 2, g = tid & 3;
            const int jb = kt >> 9, ko = kt & (PD - 1);
            cp16(sbA + buf * 4096 + (uint32_t)awd_g(row, g) * 4,
                 g_h + off[row * 4 + jb] + ko + g * 8);
        }
    };
    auto issueB1 = [&](int buf, int kt) {
        #pragma unroll
        for (int p = 0; p < 4; p++) {
            const int n = p * 128 + (tid >> 2), g = tid & 3;
            cp16(sbB + buf * 32768 + (uint32_t)awd_g(n, g) * 4,
                 g_W1t + (size_t)n * K1 + kt + g * 8);
        }
    };
    auto issueB2 = [&](int buf, int kt) {
        #pragma unroll
        for (int p = 0; p < 2; p++) {
            const int n = p * 128 + (tid >> 2), g = tid & 3;
            cp16(sbB + buf * 32768 + (uint32_t)awd_g(n, g) * 4,
                 g_W2t + (size_t)n * K2 + kt + g * 8);
        }
    };

    // ======================= Phase 1: x1 = gelu(A@W1+b1) =====================
    float acc[2][8][4];
    #pragma unroll
    for (int mf = 0; mf < 2; mf++)
        #pragma unroll
        for (int nf = 0; nf < 8; nf++)
            #pragma unroll
            for (int q = 0; q < 4; q++) acc[mf][nf][q] = 0.0f;

    issueA(0, 0);  issueB1(0, 0);  CP_COMMIT();
    issueA(1, KC); issueB1(1, KC); CP_COMMIT();

    for (int s = 0; s < NSTG1; ++s) {
        CP_WAIT(1);
        __syncthreads();
        if (s + 2 < NSTG1) { issueA((s + 2) % 3, (s + 2) * KC); issueB1((s + 2) % 3, (s + 2) * KC); }
        CP_COMMIT();

        const uint32_t Ab = sbA + (s % 3) * 4096;
        const uint32_t Bb = sbB + (s % 3) * 32768;
        #pragma unroll
        for (int ks = 0; ks < 2; ++ks) {
            const uint32_t ao = Ab + (ks ? aoff1 : aoff0);
            const uint32_t bo = Bb + (ks ? boff1 : boff0);
            uint32_t a[2][4];
            ldsm4(a[0], ao);
            ldsm4(a[1], ao + 1024);
            uint32_t bf[8][2];
            #pragma unroll
            for (int p = 0; p < 4; p++) {
                uint32_t t4[4];
                ldsm4(t4, bo + (uint32_t)p * 1024);
                bf[2 * p][0]     = t4[0]; bf[2 * p][1]     = t4[1];
                bf[2 * p + 1][0] = t4[2]; bf[2 * p + 1][1] = t4[3];
            }
            #pragma unroll
            for (int nf = 0; nf < 8; nf++) {
                mma_f16(acc[0][nf], a[0], bf[nf]);
                mma_f16(acc[1][nf], a[1], bf[nf]);
            }
        }
    }
    __syncthreads();

    // epilogue 1: gelu(+b1) -> half pairs into swizzled x1
    #pragma unroll
    for (int mf = 0; mf < 2; mf++) {
        const int r0 = wm * 32 + mf * 16 + lq;
        #pragma unroll
        for (int nf = 0; nf < 8; nf++) {
            const int col = wn * 64 + nf * 8 + 2 * lr;
            const int kp  = wn * 32 + nf * 4 + lr;
            const float* c = acc[mf][nf];
            __half2 lo = __floats2half2_rn(gelu_exact(c[0] + b1s[col]),
                                           gelu_exact(c[1] + b1s[col + 1]));
            __half2 hi = __floats2half2_rn(gelu_exact(c[2] + b1s[col]),
                                           gelu_exact(c[3] + b1s[col + 1]));
            smw[WX1 + xwd_w(r0, kp)]     = *(const uint32_t*)&lo;
            smw[WX1 + xwd_w(r0 + 8, kp)] = *(const uint32_t*)&hi;
        }
    }
    __syncthreads();

    // ================= Phase 2: y = gelu(x1@W2+b2); out = sp(y.W3+b3) ========
    float acc2[2][4][4];
    #pragma unroll
    for (int mf = 0; mf < 2; mf++)
        #pragma unroll
        for (int nf = 0; nf < 4; nf++)
            #pragma unroll
            for (int q = 0; q < 4; q++) acc2[mf][nf][q] = 0.0f;

    issueB2(0, 0);  CP_COMMIT();
    issueB2(1, KC); CP_COMMIT();

    for (int s = 0; s < NSTG2; ++s) {
        CP_WAIT(1);
        __syncthreads();
        if (s + 2 < NSTG2) issueB2((s + 2) % 3, (s + 2) * KC);
        CP_COMMIT();

        const uint32_t Bb = sbB + (s % 3) * 32768;
        #pragma unroll
        for (int ks = 0; ks < 2; ++ks) {
            // x1 ldmatrix: row arow(+16 per mf), granule gb = s*4 + ks*2 + ghalf
            const int gb = s * 4 + ks * 2 + ghalf;
            uint32_t a[2][4];
            {
                const int r = arow;
                const uint32_t xa = sbX + (uint32_t)(r * 256 + 4 * (gb ^ (r & 7))) * 4;
                ldsm4(a[0], xa);
                const int r2 = arow + 16;
                const uint32_t xa2 = sbX + (uint32_t)(r2 * 256 + 4 * (gb ^ (r2 & 7))) * 4;
                ldsm4(a[1], xa2);
            }
            const uint32_t bo = Bb + (ks ? b2off1 : b2off0);
            uint32_t bf[4][2];
            #pragma unroll
            for (int p = 0; p < 2; p++) {
                uint32_t t4[4];
                ldsm4(t4, bo + (uint32_t)p * 1024);
                bf[2 * p][0]     = t4[0]; bf[2 * p][1]     = t4[1];
                bf[2 * p + 1][0] = t4[2]; bf[2 * p + 1][1] = t4[3];
            }
            #pragma unroll
            for (int nf = 0; nf < 4; nf++) {
                mma_f16(acc2[0][nf], a[0], bf[nf]);
                mma_f16(acc2[1][nf], a[1], bf[nf]);
            }
        }
    }

    // fused epilogue: gelu(+b2) . W3 -> quad-shuffle reduce -> softplus
    const float b3v = b3[0];
    #pragma unroll
    for (int mf = 0; mf < 2; mf++) {
        float p0 = 0.0f, p1 = 0.0f;
        #pragma unroll
        for (int nf = 0; nf < 4; nf++) {
            const int col = wn * 32 + nf * 8 + 2 * lr;
            const float* c = acc2[mf][nf];
            p0 = fmaf(gelu_exact(c[0] + b2s[col]),     w3s[col],     p0);
            p0 = fmaf(gelu_exact(c[1] + b2s[col + 1]), w3s[col + 1], p0);
            p1 = fmaf(gelu_exact(c[2] + b2s[col]),     w3s[col],     p1);
            p1 = fmaf(gelu_exact(c[3] + b2s[col + 1]), w3s[col + 1], p1);
        }
        p0 += __shfl_xor_sync(0xffffffffu, p0, 1);
        p0 += __shfl_xor_sync(0xffffffffu, p0, 2);
        p1 += __shfl_xor_sync(0xffffffffu, p1, 1);
        p1 += __shfl_xor_sync(0xffffffffu, p1, 2);
        if (lr == 0) {
            const int r0 = wm * 32 + mf * 16 + lq;
            red[r0 * 8 + wn]       = p0;
            red[(r0 + 8) * 8 + wn] = p1;
        }
    }
    __syncthreads();

    if (tid < MTILE) {
        const float* rr = &red[tid * 8];
        const float ssum = rr[0] + rr[1] + rr[2] + rr[3] + rr[4] + rr[5] + rr[6] + rr[7];
        out[row0 + tid] = softplus_stable(ssum + b3v);
    }
}

extern "C" void kernel_launch(void* const* d_in, const int* in_sizes, int n_in,
                              void* d_out, int out_size)
{
    const float* h   = (const float*)d_in[0];
    const void*  idx = (const void*)d_in[1];
    const float* W1  = (const float*)d_in[2];
    const float* b1  = (const float*)d_in[3];
    const float* W2  = (const float*)d_in[4];
    const float* b2  = (const float*)d_in[5];
    const float* W3  = (const float*)d_in[6];
    const float* b3  = (const float*)d_in[7];
    float*       out = (float*)d_out;

    void *ph, *pw1, *pw2;
    cudaGetSymbolAddress(&ph,  g_h);
    cudaGetSymbolAddress(&pw1, g_W1t);
    cudaGetSymbolAddress(&pw2, g_W2t);

    cvt_h_kernel<<<2048, 256>>>((__half*)ph, h, PB * PN * PD / 4);
    transpose_half_kernel<<<dim3(N1 / 32, K1 / 32), dim3(32, 8)>>>((__half*)pw1, W1, K1, N1);
    transpose_half_kernel<<<dim3(N2 / 32, K2 / 32), dim3(32, 8)>>>((__half*)pw2, W2, K2, N2);

    cudaFuncSetAttribute(swap_scoring_f16,
                         cudaFuncAttributeMaxDynamicSharedMemorySize, SMEM_BYTES);
    swap_scoring_f16<<<NROWS / MTILE, 512, SMEM_BYTES>>>(
        idx, b1, b2, W3, b3, out);
}

// round 10
// speedup vs baseline: 15.5660x; 1.4079x over previous
#include <cuda_runtime.h>
#include <cuda_fp16.h>
#include <cstdint>

#define PB 8
#define PN 2048
#define PD 512
#define PS 4096
#define NROWS 32768
#define K1 2048
#define N1 512
#define K2 512
#define N2 256
#define MTILE 64
#define KC 32

// ---- device scratch ----
__device__ __half g_h[PB * PN * PD];          // fp16 h (16.8 MB)
__device__ __half g_W1t[N1 * K1];             // W1 transposed [n][k]
__device__ __half g_W2t[N2 * K2];             // W2 transposed [n][k]
__device__ float  g_Y[(size_t)(PB * PN) * 2048];  // per-(node,j) partials (134 MB)

__device__ __forceinline__ float gelu_exact(float x) {
    return 0.5f * x * (1.0f + erff(x * 0.70710678118654752440f));
}
__device__ __forceinline__ float softplus_stable(float x) {
    return fmaxf(x, 0.0f) + log1pf(expf(-fabsf(x)));
}
__device__ __forceinline__ uint32_t smem_u32(const void* p) {
    uint32_t a;
    asm("{ .reg .u64 t; cvta.to.shared.u64 t, %1; cvt.u32.u64 %0, t; }" : "=r"(a) : "l"(p));
    return a;
}
__device__ __forceinline__ void cp16(uint32_t dst, const void* src) {
    asm volatile("cp.async.cg.shared.global [%0], [%1], 16;" :: "r"(dst), "l"(src));
}
#define CP_COMMIT() asm volatile("cp.async.commit_group;" ::: "memory")
#define CP_WAIT(n)  asm volatile("cp.async.wait_group %0;" :: "n"(n) : "memory")

__device__ __forceinline__ void mma_f16(float* d, const uint32_t* a, const uint32_t* b) {
    asm volatile(
        "mma.sync.aligned.m16n8k16.row.col.f32.f16.f16.f32 "
        "{%0,%1,%2,%3}, {%4,%5,%6,%7}, {%8,%9}, {%0,%1,%2,%3};"
        : "+f"(d[0]), "+f"(d[1]), "+f"(d[2]), "+f"(d[3])
        : "r"(a[0]), "r"(a[1]), "r"(a[2]), "r"(a[3]), "r"(b[0]), "r"(b[1]));
}
__device__ __forceinline__ void ldsm4(uint32_t* r, uint32_t addr) {
    asm volatile("ldmatrix.sync.aligned.m8n8.x4.shared.b16 {%0,%1,%2,%3}, [%4];"
        : "=r"(r[0]), "=r"(r[1]), "=r"(r[2]), "=r"(r[3]) : "r"(addr));
}

// word-address swizzles (granule g = 16B = 4 words = 8 halves)
__device__ __forceinline__ int awd_g(int r, int g) { return r * 16 + 4 * (g ^ ((r >> 1) & 3)); }
__device__ __forceinline__ int xwd_w(int r, int kp) { return r * 256 + (kp ^ ((r & 7) << 2)); }

// ---- prepass kernels ----
__global__ void cvt_h_kernel(__half* __restrict__ dst, const float* __restrict__ src, int n4) {
    for (int i = blockIdx.x * blockDim.x + threadIdx.x; i < n4; i += gridDim.x * blockDim.x) {
        const float4 v = ((const float4*)src)[i];
        __half2 lo = __floats2half2_rn(v.x, v.y);
        __half2 hi = __floats2half2_rn(v.z, v.w);
        ((__half2*)dst)[2 * i]     = lo;
        ((__half2*)dst)[2 * i + 1] = hi;
    }
}
__global__ void transpose_half_kernel(__half* __restrict__ dst, const float* __restrict__ src,
                                      int K, int N) {
    __shared__ __half t[32][33];
    const int k0 = blockIdx.y * 32, n0 = blockIdx.x * 32;
    const int tx = threadIdx.x, ty = threadIdx.y;
    #pragma unroll
    for (int i = 0; i < 32; i += 8)
        t[ty + i][tx] = __float2half_rn(src[(size_t)(k0 + ty + i) * N + n0 + tx]);
    __syncthreads();
    #pragma unroll
    for (int i = 0; i < 32; i += 8)
        dst[(size_t)(n0 + ty + i) * K + k0 + tx] = t[tx][ty + i];
}

// ============================================================================
// Kernel A: Y[bn, j*512+d] = h_flat[bn, :512] @ W1[j*512:+512, d]   (fp32 out)
// Grid: (256 m-tiles, 4 j). 512 thr, warp tile 32x64, K=512, KC=32, 3 bufs.
// ============================================================================
#define PWA0 0
#define PWB0 3072
#define PRE_SMEM_BYTES ((3072 + 24576) * 4)

__global__ void __launch_bounds__(512, 1)
precompute_y_kernel()
{
    extern __shared__ uint32_t smw[];
    const uint32_t sb  = smem_u32(smw);
    const uint32_t sbA = sb + PWA0 * 4;
    const uint32_t sbB = sb + PWB0 * 4;

    const int tid  = threadIdx.x;
    const int lane = tid & 31;
    const int wid  = tid >> 5;
    const int lq   = lane >> 2;
    const int lr   = lane & 3;
    const int wm   = wid >> 3;
    const int wn   = wid & 7;

    const int row0 = blockIdx.x * MTILE;
    const int j    = blockIdx.y;

    const int arow  = wm * 32 + (lane & 15);
    const int ghalf = lane >> 4;
    const uint32_t aoff0 = (uint32_t)awd_g(arow, 0 + ghalf) * 4;
    const uint32_t aoff1 = (uint32_t)awd_g(arow, 2 + ghalf) * 4;
    const int bn0 = wn * 64 + ((lane >> 4) << 3) + (lane & 7);
    const int bg  = (lane >> 3) & 1;
    const uint32_t boff0 = (uint32_t)awd_g(bn0, 0 + bg) * 4;
    const uint32_t boff1 = (uint32_t)awd_g(bn0, 2 + bg) * 4;

    auto issueA = [&](int buf, int kt) {
        if (tid < 256) {
            const int row = tid >> 2, g = tid & 3;
            cp16(sbA + buf * 4096 + (uint32_t)awd_g(row, g) * 4,
                 g_h + (size_t)(row0 + row) * PD + kt + g * 8);
        }
    };
    auto issueB = [&](int buf, int kt) {
        #pragma unroll
        for (int p = 0; p < 4; p++) {
            const int n = p * 128 + (tid >> 2), g = tid & 3;
            cp16(sbB + buf * 32768 + (uint32_t)awd_g(n, g) * 4,
                 g_W1t + (size_t)n * K1 + j * 512 + kt + g * 8);
        }
    };

    float acc[2][8][4];
    #pragma unroll
    for (int mf = 0; mf < 2; mf++)
        #pragma unroll
        for (int nf = 0; nf < 8; nf++)
            #pragma unroll
            for (int q = 0; q < 4; q++) acc[mf][nf][q] = 0.0f;

    const int NST = PD / KC;   // 16
    issueA(0, 0);  issueB(0, 0);  CP_COMMIT();
    issueA(1, KC); issueB(1, KC); CP_COMMIT();

    for (int s = 0; s < NST; ++s) {
        CP_WAIT(1);
        __syncthreads();
        if (s + 2 < NST) { issueA((s + 2) % 3, (s + 2) * KC); issueB((s + 2) % 3, (s + 2) * KC); }
        CP_COMMIT();

        const uint32_t Ab = sbA + (s % 3) * 4096;
        const uint32_t Bb = sbB + (s % 3) * 32768;
        #pragma unroll
        for (int ks = 0; ks < 2; ++ks) {
            const uint32_t ao = Ab + (ks ? aoff1 : aoff0);
            const uint32_t bo = Bb + (ks ? boff1 : boff0);
            uint32_t a[2][4];
            ldsm4(a[0], ao);
            ldsm4(a[1], ao + 1024);
            uint32_t bf[8][2];
            #pragma unroll
            for (int p = 0; p < 4; p++) {
                uint32_t t4[4];
                ldsm4(t4, bo + (uint32_t)p * 1024);
                bf[2 * p][0]     = t4[0]; bf[2 * p][1]     = t4[1];
                bf[2 * p + 1][0] = t4[2]; bf[2 * p + 1][1] = t4[3];
            }
            #pragma unroll
            for (int nf = 0; nf < 8; nf++) {
                mma_f16(acc[0][nf], a[0], bf[nf]);
                mma_f16(acc[1][nf], a[1], bf[nf]);
            }
        }
        __syncthreads();
    }

    // store fp32 partials (no bias, no gelu — both applied after the j-sum)
    #pragma unroll
    for (int mf = 0; mf < 2; mf++) {
        const int r = row0 + wm * 32 + mf * 16 + lq;
        #pragma unroll
        for (int nf = 0; nf < 8; nf++) {
            const int c = wn * 64 + nf * 8 + 2 * lr;
            const float* cc = acc[mf][nf];
            *(float2*)&g_Y[(size_t)r * 2048 + j * 512 + c]       = make_float2(cc[0], cc[1]);
            *(float2*)&g_Y[(size_t)(r + 8) * 2048 + j * 512 + c] = make_float2(cc[2], cc[3]);
        }
    }
}

// ============================================================================
// Kernel B: gather-sum Y -> gelu -> x1 (smem fp16) -> GEMM2 -> W3 -> softplus
// ============================================================================
#define WX1   0
#define WB0s  16384                   // B bufs: 3 x 4096 words
#define WB1S  (WB0s + 12288)
#define WB2S  (WB1S + 512)
#define WW3S  (WB2S + 256)
#define WRED  (WW3S + 256)
#define WNODE (WRED + 512)
#define WMODE (WNODE + 256)
#define SC_SMEM_BYTES ((WMODE + 4) * 4)
#define NSTG2 (K2 / KC)               // 16

__global__ void __launch_bounds__(512, 1)
swap_scoring_g(const void* __restrict__ indices_raw,
               const float* __restrict__ b1,
               const float* __restrict__ b2,
               const float* __restrict__ W3,
               const float* __restrict__ b3,
               float* __restrict__ out)
{
    extern __shared__ uint32_t smw[];
    float* b1s = (float*)(smw + WB1S);
    float* b2s = (float*)(smw + WB2S);
    float* w3s = (float*)(smw + WW3S);
    float* red = (float*)(smw + WRED);
    int*   nodes = (int*)(smw + WNODE);

    const uint32_t sb  = smem_u32(smw);
    const uint32_t sbB = sb + WB0s * 4;
    const uint32_t sbX = sb + WX1 * 4;

    const int tid  = threadIdx.x;
    const int lane = tid & 31;
    const int wid  = tid >> 5;
    const int lq   = lane >> 2;
    const int lr   = lane & 3;
    const int wm   = wid >> 3;
    const int wn   = wid & 7;

    const int row0 = blockIdx.x * MTILE;
    const int bb   = row0 / PS;
    const int s0   = row0 % PS;

    if (tid == 0) {
        const int* p32 = (const int*)indices_raw;
        int is64 = 1;
        #pragma unroll
        for (int t = 0; t < 32; t++)
            if (p32[2 * t + 1] != 0) { is64 = 0; break; }
        *(int*)(smw + WMODE) = is64;
    }
    b1s[tid] = b1[tid];
    if (tid < 256) { b2s[tid] = b2[tid]; w3s[tid] = W3[tid]; }
    __syncthreads();

    const int is64 = *(const int*)(smw + WMODE);
    if (tid < MTILE * 4) {
        const int m = tid >> 2, j = tid & 3;
        const long long e = ((long long)(bb * PS + s0 + m)) * 4 + j;
        int idx;
        if (is64) idx = (int)((const long long*)indices_raw)[e];
        else      idx = ((const int*)indices_raw)[e];
        nodes[m * 4 + j] = bb * PN + (idx & (PN - 1));
    }
    __syncthreads();

    // ---------- gather-sum: preact = sum_j Y[node_j, j*512:+512] ----------
    {
        const int rg = tid >> 3;      // row 0..63
        const int l8 = tid & 7;
        float4 s4[16];
        #pragma unroll
        for (int i = 0; i < 16; i++) s4[i] = make_float4(0.f, 0.f, 0.f, 0.f);
        #pragma unroll
        for (int j = 0; j < 4; j++) {
            const float4* base =
                (const float4*)(g_Y + (size_t)nodes[rg * 4 + j] * 2048 + j * 512);
            #pragma unroll
            for (int i = 0; i < 16; i++) {
                const float4 v = __ldg(base + i * 8 + l8);
                s4[i].x += v.x; s4[i].y += v.y; s4[i].z += v.z; s4[i].w += v.w;
            }
        }
        #pragma unroll
        for (int i = 0; i < 16; i++) {
            const int col = (i * 8 + l8) * 4;
            const float g0 = gelu_exact(s4[i].x + b1s[col]);
            const float g1 = gelu_exact(s4[i].y + b1s[col + 1]);
            const float g2 = gelu_exact(s4[i].z + b1s[col + 2]);
            const float g3 = gelu_exact(s4[i].w + b1s[col + 3]);
            const __half2 h01 = __floats2half2_rn(g0, g1);
            const __half2 h23 = __floats2half2_rn(g2, g3);
            const int kp = col >> 1;
            smw[WX1 + xwd_w(rg, kp)]     = *(const uint32_t*)&h01;
            smw[WX1 + xwd_w(rg, kp + 1)] = *(const uint32_t*)&h23;
        }
    }
    __syncthreads();

    // ---------------- GEMM2: y = gelu(x1@W2+b2); out = sp(y.W3+b3) ----------
    const int arow  = wm * 32 + (lane & 15);
    const int ghalf = lane >> 4;
    const int bn2 = wn * 32 + ((lane >> 4) << 3) + (lane & 7);
    const int bg  = (lane >> 3) & 1;
    const uint32_t b2off0 = (uint32_t)awd_g(bn2, 0 + bg) * 4;
    const uint32_t b2off1 = (uint32_t)awd_g(bn2, 2 + bg) * 4;

    auto issueB2 = [&](int buf, int kt) {
        #pragma unroll
        for (int p = 0; p < 2; p++) {
            const int n = p * 128 + (tid >> 2), g = tid & 3;
            cp16(sbB + buf * 16384 + (uint32_t)awd_g(n, g) * 4,
                 g_W2t + (size_t)n * K2 + kt + g * 8);
        }
    };

    float acc2[2][4][4];
    #pragma unroll
    for (int mf = 0; mf < 2; mf++)
        #pragma unroll
        for (int nf = 0; nf < 4; nf++)
            #pragma unroll
            for (int q = 0; q < 4; q++) acc2[mf][nf][q] = 0.0f;

    issueB2(0, 0);  CP_COMMIT();
    issueB2(1, KC); CP_COMMIT();

    for (int s = 0; s < NSTG2; ++s) {
        CP_WAIT(1);
        __syncthreads();
        if (s + 2 < NSTG2) issueB2((s + 2) % 3, (s + 2) * KC);
        CP_COMMIT();

        const uint32_t Bb = sbB + (s % 3) * 16384;
        #pragma unroll
        for (int ks = 0; ks < 2; ++ks) {
            const int gb = s * 4 + ks * 2 + ghalf;
            uint32_t a[2][4];
            {
                const int r = arow;
                ldsm4(a[0], sbX + (uint32_t)(r * 256 + 4 * (gb ^ (r & 7))) * 4);
                const int r2 = arow + 16;
                ldsm4(a[1], sbX + (uint32_t)(r2 * 256 + 4 * (gb ^ (r2 & 7))) * 4);
            }
            const uint32_t bo = Bb + (ks ? b2off1 : b2off0);
            uint32_t bf[4][2];
            #pragma unroll
            for (int p = 0; p < 2; p++) {
                uint32_t t4[4];
                ldsm4(t4, bo + (uint32_t)p * 1024);
                bf[2 * p][0]     = t4[0]; bf[2 * p][1]     = t4[1];
                bf[2 * p + 1][0] = t4[2]; bf[2 * p + 1][1] = t4[3];
            }
            #pragma unroll
            for (int nf = 0; nf < 4; nf++) {
                mma_f16(acc2[0][nf], a[0], bf[nf]);
                mma_f16(acc2[1][nf], a[1], bf[nf]);
            }
        }
        __syncthreads();
    }

    const float b3v = b3[0];
    #pragma unroll
    for (int mf = 0; mf < 2; mf++) {
        float p0 = 0.0f, p1 = 0.0f;
        #pragma unroll
        for (int nf = 0; nf < 4; nf++) {
            const int col = wn * 32 + nf * 8 + 2 * lr;
            const float* c = acc2[mf][nf];
            p0 = fmaf(gelu_exact(c[0] + b2s[col]),     w3s[col],     p0);
            p0 = fmaf(gelu_exact(c[1] + b2s[col + 1]), w3s[col + 1], p0);
            p1 = fmaf(gelu_exact(c[2] + b2s[col]),     w3s[col],     p1);
            p1 = fmaf(gelu_exact(c[3] + b2s[col + 1]), w3s[col + 1], p1);
        }
        p0 += __shfl_xor_sync(0xffffffffu, p0, 1);
        p0 += __shfl_xor_sync(0xffffffffu, p0, 2);
        p1 += __shfl_xor_sync(0xffffffffu, p1, 1);
        p1 += __shfl_xor_sync(0xffffffffu, p1, 2);
        if (lr == 0) {
            const int r0 = wm * 32 + mf * 16 + lq;
            red[r0 * 8 + wn]       = p0;
            red[(r0 + 8) * 8 + wn] = p1;
        }
    }
    __syncthreads();

    if (tid < MTILE) {
        const float* rr = &red[tid * 8];
        const float ssum = rr[0] + rr[1] + rr[2] + rr[3] + rr[4] + rr[5] + rr[6] + rr[7];
        out[row0 + tid] = softplus_stable(ssum + b3v);
    }
}

extern "C" void kernel_launch(void* const* d_in, const int* in_sizes, int n_in,
                              void* d_out, int out_size)
{
    const float* h   = (const float*)d_in[0];
    const void*  idx = (const void*)d_in[1];
    const float* W1  = (const float*)d_in[2];
    const float* b1  = (const float*)d_in[3];
    const float* W2  = (const float*)d_in[4];
    const float* b2  = (const float*)d_in[5];
    const float* W3  = (const float*)d_in[6];
    const float* b3  = (const float*)d_in[7];
    float*       out = (float*)d_out;

    void *ph, *pw1, *pw2;
    cudaGetSymbolAddress(&ph,  g_h);
    cudaGetSymbolAddress(&pw1, g_W1t);
    cudaGetSymbolAddress(&pw2, g_W2t);

    cvt_h_kernel<<<2048, 256>>>((__half*)ph, h, PB * PN * PD / 4);
    transpose_half_kernel<<<dim3(N1 / 32, K1 / 32), dim3(32, 8)>>>((__half*)pw1, W1, K1, N1);
    transpose_half_kernel<<<dim3(N2 / 32, K2 / 32), dim3(32, 8)>>>((__half*)pw2, W2, K2, N2);

    cudaFuncSetAttribute(precompute_y_kernel,
                         cudaFuncAttributeMaxDynamicSharedMemorySize, PRE_SMEM_BYTES);
    precompute_y_kernel<<<dim3(PB * PN / MTILE, 4), 512, PRE_SMEM_BYTES>>>();

    cudaFuncSetAttribute(swap_scoring_g,
                         cudaFuncAttributeMaxDynamicSharedMemorySize, SC_SMEM_BYTES);
    swap_scoring_g<<<NROWS / MTILE, 512, SC_SMEM_BYTES>>>(
        idx, b1, b2, W3, b3, out);
}

// round 11
// speedup vs baseline: 16.5219x; 1.0614x over previous
#include <cuda_runtime.h>
#include <cuda_fp16.h>
#include <cstdint>

#define PB 8
#define PN 2048
#define PD 512
#define PS 4096
#define NROWS 32768
#define K1 2048
#define N1 512
#define K2 512
#define N2 256
#define MTILE 64
#define KC 32

// ---- device scratch ----
__device__ __half g_h[PB * PN * PD];          // fp16 h (16.8 MB)
__device__ __half g_W1t[N1 * K1];             // W1 transposed [n][k]
__device__ __half g_W2t[N2 * K2];             // W2 transposed [n][k]
__device__ __half g_Y[(size_t)(PB * PN) * 2048];  // per-(node,j) partials, fp16 (67 MB)

__device__ __forceinline__ float gelu_exact(float x) {
    return 0.5f * x * (1.0f + erff(x * 0.70710678118654752440f));
}
__device__ __forceinline__ float softplus_stable(float x) {
    return fmaxf(x, 0.0f) + log1pf(expf(-fabsf(x)));
}
__device__ __forceinline__ uint32_t smem_u32(const void* p) {
    uint32_t a;
    asm("{ .reg .u64 t; cvta.to.shared.u64 t, %1; cvt.u32.u64 %0, t; }" : "=r"(a) : "l"(p));
    return a;
}
__device__ __forceinline__ void cp16(uint32_t dst, const void* src) {
    asm volatile("cp.async.cg.shared.global [%0], [%1], 16;" :: "r"(dst), "l"(src));
}
#define CP_COMMIT() asm volatile("cp.async.commit_group;" ::: "memory")
#define CP_WAIT(n)  asm volatile("cp.async.wait_group %0;" :: "n"(n) : "memory")

__device__ __forceinline__ void mma_f16(float* d, const uint32_t* a, const uint32_t* b) {
    asm volatile(
        "mma.sync.aligned.m16n8k16.row.col.f32.f16.f16.f32 "
        "{%0,%1,%2,%3}, {%4,%5,%6,%7}, {%8,%9}, {%0,%1,%2,%3};"
        : "+f"(d[0]), "+f"(d[1]), "+f"(d[2]), "+f"(d[3])
        : "r"(a[0]), "r"(a[1]), "r"(a[2]), "r"(a[3]), "r"(b[0]), "r"(b[1]));
}
__device__ __forceinline__ void ldsm4(uint32_t* r, uint32_t addr) {
    asm volatile("ldmatrix.sync.aligned.m8n8.x4.shared.b16 {%0,%1,%2,%3}, [%4];"
        : "=r"(r[0]), "=r"(r[1]), "=r"(r[2]), "=r"(r[3]) : "r"(addr));
}

// word-address swizzles (granule g = 16B = 4 words = 8 halves)
__device__ __forceinline__ int awd_g(int r, int g) { return r * 16 + 4 * (g ^ ((r >> 1) & 3)); }
__device__ __forceinline__ int xwd_w(int r, int kp) { return r * 256 + (kp ^ ((r & 7) << 2)); }

// ---- prepass kernels ----
__global__ void cvt_h_kernel(__half* __restrict__ dst, const float* __restrict__ src, int n4) {
    for (int i = blockIdx.x * blockDim.x + threadIdx.x; i < n4; i += gridDim.x * blockDim.x) {
        const float4 v = ((const float4*)src)[i];
        __half2 lo = __floats2half2_rn(v.x, v.y);
        __half2 hi = __floats2half2_rn(v.z, v.w);
        ((__half2*)dst)[2 * i]     = lo;
        ((__half2*)dst)[2 * i + 1] = hi;
    }
}
__global__ void transpose_half_kernel(__half* __restrict__ dst, const float* __restrict__ src,
                                      int K, int N) {
    __shared__ __half t[32][33];
    const int k0 = blockIdx.y * 32, n0 = blockIdx.x * 32;
    const int tx = threadIdx.x, ty = threadIdx.y;
    #pragma unroll
    for (int i = 0; i < 32; i += 8)
        t[ty + i][tx] = __float2half_rn(src[(size_t)(k0 + ty + i) * N + n0 + tx]);
    __syncthreads();
    #pragma unroll
    for (int i = 0; i < 32; i += 8)
        dst[(size_t)(n0 + ty + i) * K + k0 + tx] = t[tx][ty + i];
}

// ============================================================================
// Kernel A: Y[bn, j*512+d] = h_flat[bn, :512] @ W1[j*512:+512, d]   (fp16 out)
// ============================================================================
#define PWA0 0
#define PWB0 3072
#define PRE_SMEM_BYTES ((3072 + 24576) * 4)

__global__ void __launch_bounds__(512, 1)
precompute_y_kernel()
{
    extern __shared__ uint32_t smw[];
    const uint32_t sb  = smem_u32(smw);
    const uint32_t sbA = sb + PWA0 * 4;
    const uint32_t sbB = sb + PWB0 * 4;

    const int tid  = threadIdx.x;
    const int lane = tid & 31;
    const int wid  = tid >> 5;
    const int lq   = lane >> 2;
    const int lr   = lane & 3;
    const int wm   = wid >> 3;
    const int wn   = wid & 7;

    const int row0 = blockIdx.x * MTILE;
    const int j    = blockIdx.y;

    const int arow  = wm * 32 + (lane & 15);
    const int ghalf = lane >> 4;
    const uint32_t aoff0 = (uint32_t)awd_g(arow, 0 + ghalf) * 4;
    const uint32_t aoff1 = (uint32_t)awd_g(arow, 2 + ghalf) * 4;
    const int bn0 = wn * 64 + ((lane >> 4) << 3) + (lane & 7);
    const int bg  = (lane >> 3) & 1;
    const uint32_t boff0 = (uint32_t)awd_g(bn0, 0 + bg) * 4;
    const uint32_t boff1 = (uint32_t)awd_g(bn0, 2 + bg) * 4;

    auto issueA = [&](int buf, int kt) {
        if (tid < 256) {
            const int row = tid >> 2, g = tid & 3;
            cp16(sbA + buf * 4096 + (uint32_t)awd_g(row, g) * 4,
                 g_h + (size_t)(row0 + row) * PD + kt + g * 8);
        }
    };
    auto issueB = [&](int buf, int kt) {
        #pragma unroll
        for (int p = 0; p < 4; p++) {
            const int n = p * 128 + (tid >> 2), g = tid & 3;
            cp16(sbB + buf * 32768 + (uint32_t)awd_g(n, g) * 4,
                 g_W1t + (size_t)n * K1 + j * 512 + kt + g * 8);
        }
    };

    float acc[2][8][4];
    #pragma unroll
    for (int mf = 0; mf < 2; mf++)
        #pragma unroll
        for (int nf = 0; nf < 8; nf++)
            #pragma unroll
            for (int q = 0; q < 4; q++) acc[mf][nf][q] = 0.0f;

    const int NST = PD / KC;   // 16
    issueA(0, 0);  issueB(0, 0);  CP_COMMIT();
    issueA(1, KC); issueB(1, KC); CP_COMMIT();

    for (int s = 0; s < NST; ++s) {
        CP_WAIT(1);
        __syncthreads();
        if (s + 2 < NST) { issueA((s + 2) % 3, (s + 2) * KC); issueB((s + 2) % 3, (s + 2) * KC); }
        CP_COMMIT();

        const uint32_t Ab = sbA + (s % 3) * 4096;
        const uint32_t Bb = sbB + (s % 3) * 32768;
        #pragma unroll
        for (int ks = 0; ks < 2; ++ks) {
            const uint32_t ao = Ab + (ks ? aoff1 : aoff0);
            const uint32_t bo = Bb + (ks ? boff1 : boff0);
            uint32_t a[2][4];
            ldsm4(a[0], ao);
            ldsm4(a[1], ao + 1024);
            uint32_t bf[8][2];
            #pragma unroll
            for (int p = 0; p < 4; p++) {
                uint32_t t4[4];
                ldsm4(t4, bo + (uint32_t)p * 1024);
                bf[2 * p][0]     = t4[0]; bf[2 * p][1]     = t4[1];
                bf[2 * p + 1][0] = t4[2]; bf[2 * p + 1][1] = t4[3];
            }
            #pragma unroll
            for (int nf = 0; nf < 8; nf++) {
                mma_f16(acc[0][nf], a[0], bf[nf]);
                mma_f16(acc[1][nf], a[1], bf[nf]);
            }
        }
    }

    // store fp16 partials (no bias/gelu — applied after the j-sum)
    #pragma unroll
    for (int mf = 0; mf < 2; mf++) {
        const int r = row0 + wm * 32 + mf * 16 + lq;
        #pragma unroll
        for (int nf = 0; nf < 8; nf++) {
            const int c = wn * 64 + nf * 8 + 2 * lr;
            const float* cc = acc[mf][nf];
            const __half2 p01 = __floats2half2_rn(cc[0], cc[1]);
            const __half2 p23 = __floats2half2_rn(cc[2], cc[3]);
            *(__half2*)&g_Y[(size_t)r * 2048 + j * 512 + c]       = p01;
            *(__half2*)&g_Y[(size_t)(r + 8) * 2048 + j * 512 + c] = p23;
        }
    }
}

// ============================================================================
// Kernel B: gather-sum fp16 Y -> gelu -> x1 (smem fp16) -> GEMM2 -> softplus
// ============================================================================
#define WX1   0
#define WB0s  16384                   // B bufs: 3 x 4096 words
#define WB1S  (WB0s + 12288)
#define WB2S  (WB1S + 512)
#define WW3S  (WB2S + 256)
#define WRED  (WW3S + 256)
#define WNODE (WRED + 512)
#define WMODE (WNODE + 256)
#define SC_SMEM_BYTES ((WMODE + 4) * 4)
#define NSTG2 (K2 / KC)               // 16

__global__ void __launch_bounds__(512, 1)
swap_scoring_g(const void* __restrict__ indices_raw,
               const float* __restrict__ b1,
               const float* __restrict__ b2,
               const float* __restrict__ W3,
               const float* __restrict__ b3,
               float* __restrict__ out)
{
    extern __shared__ uint32_t smw[];
    float* b1s = (float*)(smw + WB1S);
    float* b2s = (float*)(smw + WB2S);
    float* w3s = (float*)(smw + WW3S);
    float* red = (float*)(smw + WRED);
    int*   nodes = (int*)(smw + WNODE);

    const uint32_t sb  = smem_u32(smw);
    const uint32_t sbB = sb + WB0s * 4;
    const uint32_t sbX = sb + WX1 * 4;

    const int tid  = threadIdx.x;
    const int lane = tid & 31;
    const int wid  = tid >> 5;
    const int lq   = lane >> 2;
    const int lr   = lane & 3;
    const int wm   = wid >> 3;
    const int wn   = wid & 7;

    const int row0 = blockIdx.x * MTILE;
    const int bb   = row0 / PS;
    const int s0   = row0 % PS;

    if (tid == 0) {
        const int* p32 = (const int*)indices_raw;
        int is64 = 1;
        #pragma unroll
        for (int t = 0; t < 32; t++)
            if (p32[2 * t + 1] != 0) { is64 = 0; break; }
        *(int*)(smw + WMODE) = is64;
    }
    b1s[tid] = b1[tid];
    if (tid < 256) { b2s[tid] = b2[tid]; w3s[tid] = W3[tid]; }
    __syncthreads();

    const int is64 = *(const int*)(smw + WMODE);
    if (tid < MTILE * 4) {
        const int m = tid >> 2, j = tid & 3;
        const long long e = ((long long)(bb * PS + s0 + m)) * 4 + j;
        int idx;
        if (is64) idx = (int)((const long long*)indices_raw)[e];
        else      idx = ((const int*)indices_raw)[e];
        nodes[m * 4 + j] = bb * PN + (idx & (PN - 1));
    }
    __syncthreads();

    // ---------- gather-sum: preact = sum_j Y[node_j, j*512:+512] (fp16 in) ----
    {
        const int rg = tid >> 3;      // row 0..63
        const int l8 = tid & 7;
        float s[64];
        #pragma unroll
        for (int i = 0; i < 64; i++) s[i] = 0.0f;
        #pragma unroll
        for (int j = 0; j < 4; j++) {
            const __half* base = g_Y + (size_t)nodes[rg * 4 + j] * 2048 + j * 512;
            #pragma unroll
            for (int i = 0; i < 8; i++) {
                const uint4 v = __ldg((const uint4*)(base + i * 64 + l8 * 8));
                const __half2* hp = (const __half2*)&v;
                #pragma unroll
                for (int p = 0; p < 4; p++) {
                    const float2 f = __half22float2(hp[p]);
                    s[i * 8 + 2 * p]     += f.x;
                    s[i * 8 + 2 * p + 1] += f.y;
                }
            }
        }
        #pragma unroll
        for (int i = 0; i < 8; i++) {
            const int col0 = i * 64 + l8 * 8;
            const int kp0  = col0 >> 1;         // 4-aligned granule base
            #pragma unroll
            for (int w = 0; w < 4; w++) {
                const float g0 = gelu_exact(s[i * 8 + 2 * w]     + b1s[col0 + 2 * w]);
                const float g1 = gelu_exact(s[i * 8 + 2 * w + 1] + b1s[col0 + 2 * w + 1]);
                const __half2 hh = __floats2half2_rn(g0, g1);
                smw[WX1 + xwd_w(rg, kp0 + w)] = *(const uint32_t*)&hh;
            }
        }
    }
    __syncthreads();

    // ---------------- GEMM2: y = gelu(x1@W2+b2); out = sp(y.W3+b3) ----------
    const int arow  = wm * 32 + (lane & 15);
    const int ghalf = lane >> 4;
    const int bn2 = wn * 32 + ((lane >> 4) << 3) + (lane & 7);
    const int bg  = (lane >> 3) & 1;
    const uint32_t b2off0 = (uint32_t)awd_g(bn2, 0 + bg) * 4;
    const uint32_t b2off1 = (uint32_t)awd_g(bn2, 2 + bg) * 4;

    auto issueB2 = [&](int buf, int kt) {
        #pragma unroll
        for (int p = 0; p < 2; p++) {
            const int n = p * 128 + (tid >> 2), g = tid & 3;
            cp16(sbB + buf * 16384 + (uint32_t)awd_g(n, g) * 4,
                 g_W2t + (size_t)n * K2 + kt + g * 8);
        }
    };

    float acc2[2][4][4];
    #pragma unroll
    for (int mf = 0; mf < 2; mf++)
        #pragma unroll
        for (int nf = 0; nf < 4; nf++)
            #pragma unroll
            for (int q = 0; q < 4; q++) acc2[mf][nf][q] = 0.0f;

    issueB2(0, 0);  CP_COMMIT();
    issueB2(1, KC); CP_COMMIT();

    for (int s = 0; s < NSTG2; ++s) {
        CP_WAIT(1);
        __syncthreads();
        if (s + 2 < NSTG2) issueB2((s + 2) % 3, (s + 2) * KC);
        CP_COMMIT();

        const uint32_t Bb = sbB + (s % 3) * 16384;
        #pragma unroll
        for (int ks = 0; ks < 2; ++ks) {
            const int gb = s * 4 + ks * 2 + ghalf;
            uint32_t a[2][4];
            {
                const int r = arow;
                ldsm4(a[0], sbX + (uint32_t)(r * 256 + 4 * (gb ^ (r & 7))) * 4);
                const int r2 = arow + 16;
                ldsm4(a[1], sbX + (uint32_t)(r2 * 256 + 4 * (gb ^ (r2 & 7))) * 4);
            }
            const uint32_t bo = Bb + (ks ? b2off1 : b2off0);
            uint32_t bf[4][2];
            #pragma unroll
            for (int p = 0; p < 2; p++) {
                uint32_t t4[4];
                ldsm4(t4, bo + (uint32_t)p * 1024);
                bf[2 * p][0]     = t4[0]; bf[2 * p][1]     = t4[1];
                bf[2 * p + 1][0] = t4[2]; bf[2 * p + 1][1] = t4[3];
            }
            #pragma unroll
            for (int nf = 0; nf < 4; nf++) {
                mma_f16(acc2[0][nf], a[0], bf[nf]);
                mma_f16(acc2[1][nf], a[1], bf[nf]);
            }
        }
    }

    const float b3v = b3[0];
    #pragma unroll
    for (int mf = 0; mf < 2; mf++) {
        float p0 = 0.0f, p1 = 0.0f;
        #pragma unroll
        for (int nf = 0; nf < 4; nf++) {
            const int col = wn * 32 + nf * 8 + 2 * lr;
            const float* c = acc2[mf][nf];
            p0 = fmaf(gelu_exact(c[0] + b2s[col]),     w3s[col],     p0);
            p0 = fmaf(gelu_exact(c[1] + b2s[col + 1]), w3s[col + 1], p0);
            p1 = fmaf(gelu_exact(c[2] + b2s[col]),     w3s[col],     p1);
            p1 = fmaf(gelu_exact(c[3] + b2s[col + 1]), w3s[col + 1], p1);
        }
        p0 += __shfl_xor_sync(0xffffffffu, p0, 1);
        p0 += __shfl_xor_sync(0xffffffffu, p0, 2);
        p1 += __shfl_xor_sync(0xffffffffu, p1, 1);
        p1 += __shfl_xor_sync(0xffffffffu, p1, 2);
        if (lr == 0) {
            const int r0 = wm * 32 + mf * 16 + lq;
            red[r0 * 8 + wn]       = p0;
            red[(r0 + 8) * 8 + wn] = p1;
        }
    }
    __syncthreads();

    if (tid < MTILE) {
        const float* rr = &red[tid * 8];
        const float ssum = rr[0] + rr[1] + rr[2] + rr[3] + rr[4] + rr[5] + rr[6] + rr[7];
        out[row0 + tid] = softplus_stable(ssum + b3v);
    }
}

extern "C" void kernel_launch(void* const* d_in, const int* in_sizes, int n_in,
                              void* d_out, int out_size)
{
    const float* h   = (const float*)d_in[0];
    const void*  idx = (const void*)d_in[1];
    const float* W1  = (const float*)d_in[2];
    const float* b1  = (const float*)d_in[3];
    const float* W2  = (const float*)d_in[4];
    const float* b2  = (const float*)d_in[5];
    const float* W3  = (const float*)d_in[6];
    const float* b3  = (const float*)d_in[7];
    float*       out = (float*)d_out;

    void *ph, *pw1, *pw2;
    cudaGetSymbolAddress(&ph,  g_h);
    cudaGetSymbolAddress(&pw1, g_W1t);
    cudaGetSymbolAddress(&pw2, g_W2t);

    cvt_h_kernel<<<2048, 256>>>((__half*)ph, h, PB * PN * PD / 4);
    transpose_half_kernel<<<dim3(N1 / 32, K1 / 32), dim3(32, 8)>>>((__half*)pw1, W1, K1, N1);
    transpose_half_kernel<<<dim3(N2 / 32, K2 / 32), dim3(32, 8)>>>((__half*)pw2, W2, K2, N2);

    cudaFuncSetAttribute(precompute_y_kernel,
                         cudaFuncAttributeMaxDynamicSharedMemorySize, PRE_SMEM_BYTES);
    precompute_y_kernel<<<dim3(PB * PN / MTILE, 4), 512, PRE_SMEM_BYTES>>>();

    cudaFuncSetAttribute(swap_scoring_g,
                         cudaFuncAttributeMaxDynamicSharedMemorySize, SC_SMEM_BYTES);
    swap_scoring_g<<<NROWS / MTILE, 512, SC_SMEM_BYTES>>>(
        idx, b1, b2, W3, b3, out);
}

// round 13
// speedup vs baseline: 17.8670x; 1.0814x over previous
#include <cuda_runtime.h>
#include <cuda_fp16.h>
#include <cstdint>

#define PB 8
#define PN 2048
#define PD 512
#define PS 4096
#define NROWS 32768
#define K1 2048
#define N1 512
#define K2 512
#define N2 256

// ---- device scratch ----
__device__ __half g_h[PB * PN * PD];              // fp16 h (16.8 MB)
__device__ __half g_W1t[N1 * K1];                 // W1 transposed [n][k]
__device__ __half g_W2t[N2 * K2];                 // W2 transposed [n][k]
__device__ __half g_Y[(size_t)(PB * PN) * 2048];  // per-(node,j) partials (67 MB)

__device__ __forceinline__ float gelu_exact(float x) {
    return 0.5f * x * (1.0f + erff(x * 0.70710678118654752440f));
}
__device__ __forceinline__ float softplus_stable(float x) {
    return fmaxf(x, 0.0f) + log1pf(expf(-fabsf(x)));
}
__device__ __forceinline__ uint32_t smem_u32(const void* p) {
    uint32_t a;
    asm("{ .reg .u64 t; cvta.to.shared.u64 t, %1; cvt.u32.u64 %0, t; }" : "=r"(a) : "l"(p));
    return a;
}
__device__ __forceinline__ void cp16(uint32_t dst, const void* src) {
    asm volatile("cp.async.cg.shared.global [%0], [%1], 16;" :: "r"(dst), "l"(src));
}
#define CP_COMMIT() asm volatile("cp.async.commit_group;" ::: "memory")
#define CP_WAIT(n)  asm volatile("cp.async.wait_group %0;" :: "n"(n) : "memory")

__device__ __forceinline__ void mma_f16(float* d, const uint32_t* a, const uint32_t* b) {
    asm volatile(
        "mma.sync.aligned.m16n8k16.row.col.f32.f16.f16.f32 "
        "{%0,%1,%2,%3}, {%4,%5,%6,%7}, {%8,%9}, {%0,%1,%2,%3};"
        : "+f"(d[0]), "+f"(d[1]), "+f"(d[2]), "+f"(d[3])
        : "r"(a[0]), "r"(a[1]), "r"(a[2]), "r"(a[3]), "r"(b[0]), "r"(b[1]));
}
__device__ __forceinline__ void ldsm4(uint32_t* r, uint32_t addr) {
    asm volatile("ldmatrix.sync.aligned.m8n8.x4.shared.b16 {%0,%1,%2,%3}, [%4];"
        : "=r"(r[0]), "=r"(r[1]), "=r"(r[2]), "=r"(r[3]) : "r"(addr));
}

// tiles with 64 halves (8 x 16B granules) per row, row stride 32 words:
// word = r*32 + 4*(g ^ (r&7))  -> conflict-free for cp.async stores + ldmatrix
__device__ __forceinline__ int t64w(int r, int g) { return r * 32 + 4 * (g ^ (r & 7)); }
// x1 tile: 512 halves (64 granules)/row; XOR low-3 granule bits
__device__ __forceinline__ int xwd_w(int r, int kp) { return r * 256 + (kp ^ ((r & 7) << 2)); }

// ---- prepass kernels ----
__global__ void cvt_h_kernel(__half* __restrict__ dst, const float* __restrict__ src, int n4) {
    for (int i = blockIdx.x * blockDim.x + threadIdx.x; i < n4; i += gridDim.x * blockDim.x) {
        const float4 v = ((const float4*)src)[i];
        __half2 lo = __floats2half2_rn(v.x, v.y);
        __half2 hi = __floats2half2_rn(v.z, v.w);
        ((__half2*)dst)[2 * i]     = lo;
        ((__half2*)dst)[2 * i + 1] = hi;
    }
}
__global__ void transpose_half_kernel(__half* __restrict__ dst, const float* __restrict__ src,
                                      int K, int N) {
    __shared__ __half t[32][33];
    const int k0 = blockIdx.y * 32, n0 = blockIdx.x * 32;
    const int tx = threadIdx.x, ty = threadIdx.y;
    #pragma unroll
    for (int i = 0; i < 32; i += 8)
        t[ty + i][tx] = __float2half_rn(src[(size_t)(k0 + ty + i) * N + n0 + tx]);
    __syncthreads();
    #pragma unroll
    for (int i = 0; i < 32; i += 8)
        dst[(size_t)(n0 + ty + i) * K + k0 + tx] = t[tx][ty + i];
}

// ============================================================================
// Kernel A: Y[node, n'] = h[node, :512] @ W1[j*512:+512, d]  (n' = j*512+d)
// per 128x256 tile. 512 thr, warp grid 2(m)x8(n), warp tile 64x32, KC=64,
// 8 stages, 3 buffers. Each 256-col tile lies within one j block (256|512).
// ============================================================================
#define PWA0 0                         // A bufs: 3 x 4096 words (16KB each)
#define PWB0 12288                     // B bufs: 3 x 8192 words (32KB each)
#define PRE_SMEM_BYTES ((12288 + 24576) * 4)

__global__ void __launch_bounds__(512, 1)
precompute_y_kernel()
{
    extern __shared__ uint32_t smw[];
    const uint32_t sb  = smem_u32(smw);
    const uint32_t sbA = sb + PWA0 * 4;
    const uint32_t sbB = sb + PWB0 * 4;

    const int tid  = threadIdx.x;
    const int lane = tid & 31;
    const int wid  = tid >> 5;
    const int lq   = lane >> 2;
    const int lr   = lane & 3;
    const int wm   = wid >> 3;       // 0..1 (64-row slab)
    const int wn   = wid & 7;        // 0..7 (32-col slab)

    const int row0  = blockIdx.x * 128;
    const int nbase = blockIdx.y * 256;
    const int jblk  = nbase >> 9;        // which 512-wide k-block of W1
    const int dbase = nbase & 511;       // W1t row base (output dim d)

    const int l7  = lane & 7;
    const int gha = lane >> 4;            // A/x-style granule half
    const int ghb = (lane >> 3) & 1;      // B granule half
    // A frag row bases (4 mf), all share r&7 == l7
    uint32_t abase[4];
    #pragma unroll
    for (int mf = 0; mf < 4; mf++) {
        const int r = wm * 64 + mf * 16 + (lane & 15);
        abase[mf] = (uint32_t)(r * 32) * 4;
    }
    // B frag row bases (2 ldsm groups), n&7 == l7
    const int bnr = wn * 32 + ((lane >> 4) << 3) + (lane & 7);
    const uint32_t bbase0 = (uint32_t)(bnr * 32) * 4;
    const uint32_t bbase1 = (uint32_t)((bnr + 16) * 32) * 4;

    auto issueA = [&](int buf, int kt) {
        #pragma unroll
        for (int i = 0; i < 2; i++) {
            const int idx = i * 512 + tid;
            const int row = idx >> 3, g = idx & 7;
            cp16(sbA + buf * 16384 + (uint32_t)t64w(row, g) * 4,
                 g_h + (size_t)(row0 + row) * PD + kt + g * 8);
        }
    };
    auto issueB = [&](int buf, int kt) {
        #pragma unroll
        for (int i = 0; i < 4; i++) {
            const int idx = i * 512 + tid;
            const int n = idx >> 3, g = idx & 7;
            // Y col n' = nbase+n -> W1t row d = dbase+n, k offset jblk*512
            cp16(sbB + buf * 32768 + (uint32_t)t64w(n, g) * 4,
                 g_W1t + (size_t)(dbase + n) * K1 + jblk * 512 + kt + g * 8);
        }
    };

    float acc[4][4][4];
    #pragma unroll
    for (int mf = 0; mf < 4; mf++)
        #pragma unroll
        for (int nf = 0; nf < 4; nf++)
            #pragma unroll
            for (int q = 0; q < 4; q++) acc[mf][nf][q] = 0.0f;

    const int NST = PD / 64;   // 8
    issueA(0, 0);  issueB(0, 0);  CP_COMMIT();
    issueA(1, 64); issueB(1, 64); CP_COMMIT();

    for (int s = 0; s < NST; ++s) {
        CP_WAIT(1);
        __syncthreads();
        if (s + 2 < NST) { issueA((s + 2) % 3, (s + 2) * 64); issueB((s + 2) % 3, (s + 2) * 64); }
        CP_COMMIT();

        const uint32_t Ab = sbA + (s % 3) * 16384;
        const uint32_t Bb = sbB + (s % 3) * 32768;
        #pragma unroll
        for (int ks = 0; ks < 4; ++ks) {
            const int sa  = ((2 * ks + gha) ^ l7) * 16;
            const int sbo = ((2 * ks + ghb) ^ l7) * 16;
            uint32_t a[4][4];
            #pragma unroll
            for (int mf = 0; mf < 4; mf++)
                ldsm4(a[mf], Ab + abase[mf] + sa);
            uint32_t bf[4][2];
            {
                uint32_t t4[4];
                ldsm4(t4, Bb + bbase0 + sbo);
                bf[0][0] = t4[0]; bf[0][1] = t4[1];
                bf[1][0] = t4[2]; bf[1][1] = t4[3];
                ldsm4(t4, Bb + bbase1 + sbo);
                bf[2][0] = t4[0]; bf[2][1] = t4[1];
                bf[3][0] = t4[2]; bf[3][1] = t4[3];
            }
            #pragma unroll
            for (int mf = 0; mf < 4; mf++)
                #pragma unroll
                for (int nf = 0; nf < 4; nf++)
                    mma_f16(acc[mf][nf], a[mf], bf[nf]);
        }
    }

    // store fp16 partials
    #pragma unroll
    for (int mf = 0; mf < 4; mf++) {
        const int r = row0 + wm * 64 + mf * 16 + lq;
        #pragma unroll
        for (int nf = 0; nf < 4; nf++) {
            const int c = nbase + wn * 32 + nf * 8 + 2 * lr;
            const float* cc = acc[mf][nf];
            *(__half2*)&g_Y[(size_t)r * 2048 + c]       = __floats2half2_rn(cc[0], cc[1]);
            *(__half2*)&g_Y[(size_t)(r + 8) * 2048 + c] = __floats2half2_rn(cc[2], cc[3]);
        }
    }
}

// ============================================================================
// Kernel B: gather-sum fp16 Y -> gelu -> x1 (smem) -> GEMM2 (KC=64) -> softplus
// ============================================================================
#define WX1   0
#define WB0s  16384                   // B bufs: 3 x 8192 words (32KB each)
#define WB1S  (WB0s + 24576)
#define WB2S  (WB1S + 512)
#define WW3S  (WB2S + 256)
#define WRED  (WW3S + 256)
#define WNODE (WRED + 512)
#define WMODE (WNODE + 256)
#define SC_SMEM_BYTES ((WMODE + 4) * 4)

__global__ void __launch_bounds__(512, 1)
swap_scoring_g(const void* __restrict__ indices_raw,
               const float* __restrict__ b1,
               const float* __restrict__ b2,
               const float* __restrict__ W3,
               const float* __restrict__ b3,
               float* __restrict__ out)
{
    extern __shared__ uint32_t smw[];
    float* b1s = (float*)(smw + WB1S);
    float* b2s = (float*)(smw + WB2S);
    float* w3s = (float*)(smw + WW3S);
    float* red = (float*)(smw + WRED);
    int*   nodes = (int*)(smw + WNODE);

    const uint32_t sb  = smem_u32(smw);
    const uint32_t sbB = sb + WB0s * 4;
    const uint32_t sbX = sb + WX1 * 4;

    const int tid  = threadIdx.x;
    const int lane = tid & 31;
    const int wid  = tid >> 5;
    const int lq   = lane >> 2;
    const int lr   = lane & 3;
    const int wm   = wid >> 3;
    const int wn   = wid & 7;

    const int row0 = blockIdx.x * 64;
    const int bb   = row0 / PS;
    const int s0   = row0 % PS;

    if (tid == 0) {
        const int* p32 = (const int*)indices_raw;
        int is64 = 1;
        #pragma unroll
        for (int t = 0; t < 32; t++)
            if (p32[2 * t + 1] != 0) { is64 = 0; break; }
        *(int*)(smw + WMODE) = is64;
    }
    b1s[tid] = b1[tid];
    if (tid < 256) { b2s[tid] = b2[tid]; w3s[tid] = W3[tid]; }
    __syncthreads();

    const int is64 = *(const int*)(smw + WMODE);
    if (tid < 256) {
        const int m = tid >> 2, j = tid & 3;
        const long long e = ((long long)(bb * PS + s0 + m)) * 4 + j;
        int idx;
        if (is64) idx = (int)((const long long*)indices_raw)[e];
        else      idx = ((const int*)indices_raw)[e];
        nodes[m * 4 + j] = bb * PN + (idx & (PN - 1));
    }
    __syncthreads();

    // W2 stage issue (KC=64): 256 rows x 8 granules = 2048 cp16 / 512 thr
    auto issueB2 = [&](int buf, int kt) {
        #pragma unroll
        for (int i = 0; i < 4; i++) {
            const int idx = i * 512 + tid;
            const int n = idx >> 3, g = idx & 7;
            cp16(sbB + buf * 32768 + (uint32_t)t64w(n, g) * 4,
                 g_W2t + (size_t)n * K2 + kt + g * 8);
        }
    };

    // prefetch first two W2 stages BEFORE the gather (hide under gather)
    issueB2(0, 0);  CP_COMMIT();
    issueB2(1, 64); CP_COMMIT();

    // ---------- gather-sum: preact = sum_j Y[node_j, j*512:+512] (fp16) -------
    {
        const int rg = tid >> 3;      // row 0..63
        const int l8 = tid & 7;
        float s[64];
        #pragma unroll
        for (int i = 0; i < 64; i++) s[i] = 0.0f;
        #pragma unroll
        for (int j = 0; j < 4; j++) {
            const __half* base = g_Y + (size_t)nodes[rg * 4 + j] * 2048 + j * 512;
            #pragma unroll
            for (int i = 0; i < 8; i++) {
                const uint4 v = __ldg((const uint4*)(base + i * 64 + l8 * 8));
                const __half2* hp = (const __half2*)&v;
                #pragma unroll
                for (int p = 0; p < 4; p++) {
                    const float2 f = __half22float2(hp[p]);
                    s[i * 8 + 2 * p]     += f.x;
                    s[i * 8 + 2 * p + 1] += f.y;
                }
            }
        }
        #pragma unroll
        for (int i = 0; i < 8; i++) {
            const int col0 = i * 64 + l8 * 8;
            const int kp0  = col0 >> 1;
            #pragma unroll
            for (int w = 0; w < 4; w++) {
                const float g0 = gelu_exact(s[i * 8 + 2 * w]     + b1s[col0 + 2 * w]);
                const float g1 = gelu_exact(s[i * 8 + 2 * w + 1] + b1s[col0 + 2 * w + 1]);
                const __half2 hh = __floats2half2_rn(g0, g1);
                smw[WX1 + xwd_w(rg, kp0 + w)] = *(const uint32_t*)&hh;
            }
        }
    }
    __syncthreads();

    // ---------------- GEMM2 (KC=64, 8 stages): y = gelu(x1@W2+b2) ------------
    const int arow  = wm * 32 + (lane & 15);
    const int l7    = lane & 7;
    const int gha   = lane >> 4;
    const int ghb   = (lane >> 3) & 1;
    const int bn2   = wn * 32 + ((lane >> 4) << 3) + (lane & 7);
    const uint32_t bbase0 = (uint32_t)(bn2 * 32) * 4;

    float acc2[2][4][4];
    #pragma unroll
    for (int mf = 0; mf < 2; mf++)
        #pragma unroll
        for (int nf = 0; nf < 4; nf++)
            #pragma unroll
            for (int q = 0; q < 4; q++) acc2[mf][nf][q] = 0.0f;

    const int NST2 = K2 / 64;   // 8
    for (int s = 0; s < NST2; ++s) {
        CP_WAIT(1);
        __syncthreads();
        if (s + 2 < NST2) issueB2((s + 2) % 3, (s + 2) * 64);
        CP_COMMIT();

        const uint32_t Bb = sbB + (s % 3) * 32768;
        #pragma unroll
        for (int ks = 0; ks < 4; ++ks) {
            const int gb = s * 8 + ks * 2 + gha;    // x1 granule
            uint32_t a[2][4];
            {
                const int r = arow;
                ldsm4(a[0], sbX + (uint32_t)(r * 256 + ((gb * 4) ^ ((r & 7) << 2))) * 4);
                const int r2 = arow + 16;
                ldsm4(a[1], sbX + (uint32_t)(r2 * 256 + ((gb * 4) ^ ((r2 & 7) << 2))) * 4);
            }
            const int sbo = ((2 * ks + ghb) ^ l7) * 16;
            uint32_t bf[4][2];
            {
                uint32_t t4[4];
                ldsm4(t4, Bb + bbase0 + sbo);
                bf[0][0] = t4[0]; bf[0][1] = t4[1];
                bf[1][0] = t4[2]; bf[1][1] = t4[3];
                ldsm4(t4, Bb + bbase0 + 16 * 128 + sbo);
                bf[2][0] = t4[0]; bf[2][1] = t4[1];
                bf[3][0] = t4[2]; bf[3][1] = t4[3];
            }
            #pragma unroll
            for (int nf = 0; nf < 4; nf++) {
                mma_f16(acc2[0][nf], a[0], bf[nf]);
                mma_f16(acc2[1][nf], a[1], bf[nf]);
            }
        }
    }

    const float b3v = b3[0];
    #pragma unroll
    for (int mf = 0; mf < 2; mf++) {
        float p0 = 0.0f, p1 = 0.0f;
        #pragma unroll
        for (int nf = 0; nf < 4; nf++) {
            const int col = wn * 32 + nf * 8 + 2 * lr;
            const float* c = acc2[mf][nf];
            p0 = fmaf(gelu_exact(c[0] + b2s[col]),     w3s[col],     p0);
            p0 = fmaf(gelu_exact(c[1] + b2s[col + 1]), w3s[col + 1], p0);
            p1 = fmaf(gelu_exact(c[2] + b2s[col]),     w3s[col],     p1);
            p1 = fmaf(gelu_exact(c[3] + b2s[col + 1]), w3s[col + 1], p1);
        }
        p0 += __shfl_xor_sync(0xffffffffu, p0, 1);
        p0 += __shfl_xor_sync(0xffffffffu, p0, 2);
        p1 += __shfl_xor_sync(0xffffffffu, p1, 1);
        p1 += __shfl_xor_sync(0xffffffffu, p1, 2);
        if (lr == 0) {
            const int r0 = wm * 32 + mf * 16 + lq;
            red[r0 * 8 + wn]       = p0;
            red[(r0 + 8) * 8 + wn] = p1;
        }
    }
    __syncthreads();

    if (tid < 64) {
        const float* rr = &red[tid * 8];
        const float ssum = rr[0] + rr[1] + rr[2] + rr[3] + rr[4] + rr[5] + rr[6] + rr[7];
        out[row0 + tid] = softplus_stable(ssum + b3v);
    }
}

extern "C" void kernel_launch(void* const* d_in, const int* in_sizes, int n_in,
                              void* d_out, int out_size)
{
    const float* h   = (const float*)d_in[0];
    const void*  idx = (const void*)d_in[1];
    const float* W1  = (const float*)d_in[2];
    const float* b1  = (const float*)d_in[3];
    const float* W2  = (const float*)d_in[4];
    const float* b2  = (const float*)d_in[5];
    const float* W3  = (const float*)d_in[6];
    const float* b3  = (const float*)d_in[7];
    float*       out = (float*)d_out;

    void *ph, *pw1, *pw2;
    cudaGetSymbolAddress(&ph,  g_h);
    cudaGetSymbolAddress(&pw1, g_W1t);
    cudaGetSymbolAddress(&pw2, g_W2t);

    cvt_h_kernel<<<2048, 256>>>((__half*)ph, h, PB * PN * PD / 4);
    transpose_half_kernel<<<dim3(N1 / 32, K1 / 32), dim3(32, 8)>>>((__half*)pw1, W1, K1, N1);
    transpose_half_kernel<<<dim3(N2 / 32, K2 / 32), dim3(32, 8)>>>((__half*)pw2, W2, K2, N2);

    cudaFuncSetAttribute(precompute_y_kernel,
                         cudaFuncAttributeMaxDynamicSharedMemorySize, PRE_SMEM_BYTES);
    precompute_y_kernel<<<dim3(PB * PN / 128, 8), 512, PRE_SMEM_BYTES>>>();

    cudaFuncSetAttribute(swap_scoring_g,
                         cudaFuncAttributeMaxDynamicSharedMemorySize, SC_SMEM_BYTES);
    swap_scoring_g<<<NROWS / 64, 512, SC_SMEM_BYTES>>>(
        idx, b1, b2, W3, b3, out);
}

// round 14
// speedup vs baseline: 18.1156x; 1.0139x over previous
#include <cuda_runtime.h>
#include <cuda_fp16.h>
#include <cstdint>

#define PB 8
#define PN 2048
#define PD 512
#define PS 4096
#define NROWS 32768
#define K1 2048
#define N1 512
#define K2 512
#define N2 256

// ---- device scratch ----
__device__ __half g_h[PB * PN * PD];              // fp16 h (16.8 MB)
__device__ __half g_W1t[N1 * K1];                 // W1 transposed [n][k]
__device__ __half g_W2t[N2 * K2];                 // W2 transposed [n][k]
__device__ __half g_Y[(size_t)(PB * PN) * 2048];  // per-(node,j) partials (67 MB)

__device__ __forceinline__ float gelu_exact(float x) {
    return 0.5f * x * (1.0f + erff(x * 0.70710678118654752440f));
}
__device__ __forceinline__ float softplus_stable(float x) {
    return fmaxf(x, 0.0f) + log1pf(expf(-fabsf(x)));
}
__device__ __forceinline__ uint32_t smem_u32(const void* p) {
    uint32_t a;
    asm("{ .reg .u64 t; cvta.to.shared.u64 t, %1; cvt.u32.u64 %0, t; }" : "=r"(a) : "l"(p));
    return a;
}
__device__ __forceinline__ void cp16(uint32_t dst, const void* src) {
    asm volatile("cp.async.cg.shared.global [%0], [%1], 16;" :: "r"(dst), "l"(src));
}
#define CP_COMMIT() asm volatile("cp.async.commit_group;" ::: "memory")
#define CP_WAIT(n)  asm volatile("cp.async.wait_group %0;" :: "n"(n) : "memory")

__device__ __forceinline__ void mma_f16(float* d, const uint32_t* a, const uint32_t* b) {
    asm volatile(
        "mma.sync.aligned.m16n8k16.row.col.f32.f16.f16.f32 "
        "{%0,%1,%2,%3}, {%4,%5,%6,%7}, {%8,%9}, {%0,%1,%2,%3};"
        : "+f"(d[0]), "+f"(d[1]), "+f"(d[2]), "+f"(d[3])
        : "r"(a[0]), "r"(a[1]), "r"(a[2]), "r"(a[3]), "r"(b[0]), "r"(b[1]));
}
__device__ __forceinline__ void ldsm4(uint32_t* r, uint32_t addr) {
    asm volatile("ldmatrix.sync.aligned.m8n8.x4.shared.b16 {%0,%1,%2,%3}, [%4];"
        : "=r"(r[0]), "=r"(r[1]), "=r"(r[2]), "=r"(r[3]) : "r"(addr));
}

// tiles with 64 halves (8 x 16B granules) per row, row stride 32 words:
// word = r*32 + 4*(g ^ (r&7))  -> conflict-free for cp.async stores + ldmatrix
__device__ __forceinline__ int t64w(int r, int g) { return r * 32 + 4 * (g ^ (r & 7)); }
// x1 tile: 512 halves (64 granules)/row; XOR low-3 granule bits
__device__ __forceinline__ int xwd_w(int r, int kp) { return r * 256 + (kp ^ ((r & 7) << 2)); }

// ---- prepass kernels ----
__global__ void cvt_h_kernel(__half* __restrict__ dst, const float* __restrict__ src, int n4) {
    for (int i = blockIdx.x * blockDim.x + threadIdx.x; i < n4; i += gridDim.x * blockDim.x) {
        const float4 v = ((const float4*)src)[i];
        __half2 lo = __floats2half2_rn(v.x, v.y);
        __half2 hi = __floats2half2_rn(v.z, v.w);
        ((__half2*)dst)[2 * i]     = lo;
        ((__half2*)dst)[2 * i + 1] = hi;
    }
}
__global__ void transpose_half_kernel(__half* __restrict__ dst, const float* __restrict__ src,
                                      int K, int N) {
    __shared__ __half t[32][33];
    const int k0 = blockIdx.y * 32, n0 = blockIdx.x * 32;
    const int tx = threadIdx.x, ty = threadIdx.y;
    #pragma unroll
    for (int i = 0; i < 32; i += 8)
        t[ty + i][tx] = __float2half_rn(src[(size_t)(k0 + ty + i) * N + n0 + tx]);
    __syncthreads();
    #pragma unroll
    for (int i = 0; i < 32; i += 8)
        dst[(size_t)(n0 + ty + i) * K + k0 + tx] = t[tx][ty + i];
}

// ============================================================================
// Kernel A (unchanged from R13): Y[node, n'] = h @ W1-block per 128x256 tile.
// ============================================================================
#define PWA0 0
#define PWB0 12288
#define PRE_SMEM_BYTES ((12288 + 24576) * 4)

__global__ void __launch_bounds__(512, 1)
precompute_y_kernel()
{
    extern __shared__ uint32_t smw[];
    const uint32_t sb  = smem_u32(smw);
    const uint32_t sbA = sb + PWA0 * 4;
    const uint32_t sbB = sb + PWB0 * 4;

    const int tid  = threadIdx.x;
    const int lane = tid & 31;
    const int wid  = tid >> 5;
    const int lq   = lane >> 2;
    const int lr   = lane & 3;
    const int wm   = wid >> 3;
    const int wn   = wid & 7;

    const int row0  = blockIdx.x * 128;
    const int nbase = blockIdx.y * 256;
    const int jblk  = nbase >> 9;
    const int dbase = nbase & 511;

    const int l7  = lane & 7;
    const int gha = lane >> 4;
    const int ghb = (lane >> 3) & 1;
    uint32_t abase[4];
    #pragma unroll
    for (int mf = 0; mf < 4; mf++) {
        const int r = wm * 64 + mf * 16 + (lane & 15);
        abase[mf] = (uint32_t)(r * 32) * 4;
    }
    const int bnr = wn * 32 + ((lane >> 4) << 3) + (lane & 7);
    const uint32_t bbase0 = (uint32_t)(bnr * 32) * 4;
    const uint32_t bbase1 = (uint32_t)((bnr + 16) * 32) * 4;

    auto issueA = [&](int buf, int kt) {
        #pragma unroll
        for (int i = 0; i < 2; i++) {
            const int idx = i * 512 + tid;
            const int row = idx >> 3, g = idx & 7;
            cp16(sbA + buf * 16384 + (uint32_t)t64w(row, g) * 4,
                 g_h + (size_t)(row0 + row) * PD + kt + g * 8);
        }
    };
    auto issueB = [&](int buf, int kt) {
        #pragma unroll
        for (int i = 0; i < 4; i++) {
            const int idx = i * 512 + tid;
            const int n = idx >> 3, g = idx & 7;
            cp16(sbB + buf * 32768 + (uint32_t)t64w(n, g) * 4,
                 g_W1t + (size_t)(dbase + n) * K1 + jblk * 512 + kt + g * 8);
        }
    };

    float acc[4][4][4];
    #pragma unroll
    for (int mf = 0; mf < 4; mf++)
        #pragma unroll
        for (int nf = 0; nf < 4; nf++)
            #pragma unroll
            for (int q = 0; q < 4; q++) acc[mf][nf][q] = 0.0f;

    const int NST = PD / 64;   // 8
    issueA(0, 0);  issueB(0, 0);  CP_COMMIT();
    issueA(1, 64); issueB(1, 64); CP_COMMIT();

    for (int s = 0; s < NST; ++s) {
        CP_WAIT(1);
        __syncthreads();
        if (s + 2 < NST) { issueA((s + 2) % 3, (s + 2) * 64); issueB((s + 2) % 3, (s + 2) * 64); }
        CP_COMMIT();

        const uint32_t Ab = sbA + (s % 3) * 16384;
        const uint32_t Bb = sbB + (s % 3) * 32768;
        #pragma unroll
        for (int ks = 0; ks < 4; ++ks) {
            const int sa  = ((2 * ks + gha) ^ l7) * 16;
            const int sbo = ((2 * ks + ghb) ^ l7) * 16;
            uint32_t a[4][4];
            #pragma unroll
            for (int mf = 0; mf < 4; mf++)
                ldsm4(a[mf], Ab + abase[mf] + sa);
            uint32_t bf[4][2];
            {
                uint32_t t4[4];
                ldsm4(t4, Bb + bbase0 + sbo);
                bf[0][0] = t4[0]; bf[0][1] = t4[1];
                bf[1][0] = t4[2]; bf[1][1] = t4[3];
                ldsm4(t4, Bb + bbase1 + sbo);
                bf[2][0] = t4[0]; bf[2][1] = t4[1];
                bf[3][0] = t4[2]; bf[3][1] = t4[3];
            }
            #pragma unroll
            for (int mf = 0; mf < 4; mf++)
                #pragma unroll
                for (int nf = 0; nf < 4; nf++)
                    mma_f16(acc[mf][nf], a[mf], bf[nf]);
        }
    }

    #pragma unroll
    for (int mf = 0; mf < 4; mf++) {
        const int r = row0 + wm * 64 + mf * 16 + lq;
        #pragma unroll
        for (int nf = 0; nf < 4; nf++) {
            const int c = nbase + wn * 32 + nf * 8 + 2 * lr;
            const float* cc = acc[mf][nf];
            *(__half2*)&g_Y[(size_t)r * 2048 + c]       = __floats2half2_rn(cc[0], cc[1]);
            *(__half2*)&g_Y[(size_t)(r + 8) * 2048 + c] = __floats2half2_rn(cc[2], cc[3]);
        }
    }
}

// ============================================================================
// Kernel B: 256 thr, MTILE=32, 2 CTAs/SM. gather-sum -> gelu -> x1 (smem)
//           -> GEMM2 (KC=64, 2-buffer) -> W3 dot -> softplus
// ============================================================================
#define WX1   0                        // x1: 32 rows x 256 words = 8192
#define WB0s  8192                     // B bufs: 2 x 8192 words (32KB each)
#define WB1S  (WB0s + 16384)           // b1: 512
#define WB2S  (WB1S + 512)             // b2: 256
#define WW3S  (WB2S + 256)             // W3: 256
#define WRED  (WW3S + 256)             // red: 256
#define WNODE (WRED + 256)             // nodes: 128
#define WMODE (WNODE + 128)
#define SC_SMEM_BYTES ((WMODE + 4) * 4)

__global__ void __launch_bounds__(256, 2)
swap_scoring_g(const void* __restrict__ indices_raw,
               const float* __restrict__ b1,
               const float* __restrict__ b2,
               const float* __restrict__ W3,
               const float* __restrict__ b3,
               float* __restrict__ out)
{
    extern __shared__ uint32_t smw[];
    float* b1s = (float*)(smw + WB1S);
    float* b2s = (float*)(smw + WB2S);
    float* w3s = (float*)(smw + WW3S);
    float* red = (float*)(smw + WRED);
    int*   nodes = (int*)(smw + WNODE);

    const uint32_t sb  = smem_u32(smw);
    const uint32_t sbB = sb + WB0s * 4;
    const uint32_t sbX = sb + WX1 * 4;

    const int tid  = threadIdx.x;
    const int lane = tid & 31;
    const int wid  = tid >> 5;       // 0..7
    const int lq   = lane >> 2;
    const int lr   = lane & 3;
    const int wn   = wid;            // warp owns 32 output cols

    const int row0 = blockIdx.x * 32;
    const int bb   = row0 / PS;
    const int s0   = row0 % PS;

    if (tid == 0) {
        const int* p32 = (const int*)indices_raw;
        int is64 = 1;
        #pragma unroll
        for (int t = 0; t < 32; t++)
            if (p32[2 * t + 1] != 0) { is64 = 0; break; }
        *(int*)(smw + WMODE) = is64;
    }
    for (int i = tid; i < 512; i += 256) b1s[i] = b1[i];
    b2s[tid] = b2[tid];
    w3s[tid] = W3[tid];
    __syncthreads();

    const int is64 = *(const int*)(smw + WMODE);
    if (tid < 128) {
        const int m = tid >> 2, j = tid & 3;
        const long long e = ((long long)(bb * PS + s0 + m)) * 4 + j;
        int idx;
        if (is64) idx = (int)((const long long*)indices_raw)[e];
        else      idx = ((const int*)indices_raw)[e];
        nodes[m * 4 + j] = bb * PN + (idx & (PN - 1));
    }
    __syncthreads();

    // W2 stage issue (KC=64): 256 n-rows x 8 granules = 2048 cp16 / 256 thr
    auto issueB2 = [&](int buf, int kt) {
        #pragma unroll
        for (int i = 0; i < 8; i++) {
            const int idx = i * 256 + tid;
            const int n = idx >> 3, g = idx & 7;
            cp16(sbB + buf * 32768 + (uint32_t)t64w(n, g) * 4,
                 g_W2t + (size_t)n * K2 + kt + g * 8);
        }
    };

    // prefetch first two W2 stages BEFORE the gather (hide under gather)
    issueB2(0, 0);  CP_COMMIT();
    issueB2(1, 64); CP_COMMIT();

    // ---------- gather-sum: preact = sum_j Y[node_j, j*512:+512] (fp16) -------
    {
        const int rg = tid >> 3;      // row 0..31
        const int l8 = tid & 7;
        float s[64];
        #pragma unroll
        for (int i = 0; i < 64; i++) s[i] = 0.0f;
        #pragma unroll
        for (int j = 0; j < 4; j++) {
            const __half* base = g_Y + (size_t)nodes[rg * 4 + j] * 2048 + j * 512;
            #pragma unroll
            for (int i = 0; i < 8; i++) {
                const uint4 v = __ldg((const uint4*)(base + i * 64 + l8 * 8));
                const __half2* hp = (const __half2*)&v;
                #pragma unroll
                for (int p = 0; p < 4; p++) {
                    const float2 f = __half22float2(hp[p]);
                    s[i * 8 + 2 * p]     += f.x;
                    s[i * 8 + 2 * p + 1] += f.y;
                }
            }
        }
        #pragma unroll
        for (int i = 0; i < 8; i++) {
            const int col0 = i * 64 + l8 * 8;
            const int kp0  = col0 >> 1;
            #pragma unroll
            for (int w = 0; w < 4; w++) {
                const float g0 = gelu_exact(s[i * 8 + 2 * w]     + b1s[col0 + 2 * w]);
                const float g1 = gelu_exact(s[i * 8 + 2 * w + 1] + b1s[col0 + 2 * w + 1]);
                const __half2 hh = __floats2half2_rn(g0, g1);
                smw[WX1 + xwd_w(rg, kp0 + w)] = *(const uint32_t*)&hh;
            }
        }
    }
    __syncthreads();

    // ---------------- GEMM2 (KC=64, 8 stages, 2 buffers) ---------------------
    const int arow = lane & 15;           // rows 0..31 via two ldsm groups
    const int l7   = lane & 7;
    const int gha  = lane >> 4;
    const int ghb  = (lane >> 3) & 1;
    const int bn2  = wn * 32 + ((lane >> 4) << 3) + (lane & 7);
    const uint32_t bbase0 = (uint32_t)(bn2 * 32) * 4;

    float acc2[2][4][4];
    #pragma unroll
    for (int mf = 0; mf < 2; mf++)
        #pragma unroll
        for (int nf = 0; nf < 4; nf++)
            #pragma unroll
            for (int q = 0; q < 4; q++) acc2[mf][nf][q] = 0.0f;

    const int NST2 = K2 / 64;   // 8
    for (int s = 0; s < NST2; ++s) {
        CP_WAIT(1);
        __syncthreads();

        const uint32_t Bb = sbB + (s & 1) * 32768;
        #pragma unroll
        for (int ks = 0; ks < 4; ++ks) {
            const int gb = s * 8 + ks * 2 + gha;    // x1 granule
            uint32_t a[2][4];
            {
                const int r = arow;                 // rows 0..15
                ldsm4(a[0], sbX + (uint32_t)(r * 256 + ((gb * 4) ^ ((r & 7) << 2))) * 4);
                const int r2 = arow + 16;           // rows 16..31
                ldsm4(a[1], sbX + (uint32_t)(r2 * 256 + ((gb * 4) ^ ((r2 & 7) << 2))) * 4);
            }
            const int sbo = ((2 * ks + ghb) ^ l7) * 16;
            uint32_t bf[4][2];
            {
                uint32_t t4[4];
                ldsm4(t4, Bb + bbase0 + sbo);
                bf[0][0] = t4[0]; bf[0][1] = t4[1];
                bf[1][0] = t4[2]; bf[1][1] = t4[3];
                ldsm4(t4, Bb + bbase0 + 16 * 128 + sbo);
                bf[2][0] = t4[0]; bf[2][1] = t4[1];
                bf[3][0] = t4[2]; bf[3][1] = t4[3];
            }
            #pragma unroll
            for (int nf = 0; nf < 4; nf++) {
                mma_f16(acc2[0][nf], a[0], bf[nf]);
                mma_f16(acc2[1][nf], a[1], bf[nf]);
            }
        }
        __syncthreads();    // buffer s&1 fully consumed before re-fill
        if (s + 2 < NST2) issueB2((s + 2) & 1, (s + 2) * 64);
        CP_COMMIT();        // unconditional: stage s <-> group s invariant
    }

    const float b3v = b3[0];
    #pragma unroll
    for (int mf = 0; mf < 2; mf++) {
        float p0 = 0.0f, p1 = 0.0f;
        #pragma unroll
        for (int nf = 0; nf < 4; nf++) {
            const int col = wn * 32 + nf * 8 + 2 * lr;
            const float* c = acc2[mf][nf];
            p0 = fmaf(gelu_exact(c[0] + b2s[col]),     w3s[col],     p0);
            p0 = fmaf(gelu_exact(c[1] + b2s[col + 1]), w3s[col + 1], p0);
            p1 = fmaf(gelu_exact(c[2] + b2s[col]),     w3s[col],     p1);
            p1 = fmaf(gelu_exact(c[3] + b2s[col + 1]), w3s[col + 1], p1);
        }
        p0 += __shfl_xor_sync(0xffffffffu, p0, 1);
        p0 += __shfl_xor_sync(0xffffffffu, p0, 2);
        p1 += __shfl_xor_sync(0xffffffffu, p1, 1);
        p1 += __shfl_xor_sync(0xffffffffu, p1, 2);
        if (lr == 0) {
            const int r0 = mf * 16 + lq;
            red[r0 * 8 + wn]       = p0;
            red[(r0 + 8) * 8 + wn] = p1;
        }
    }
    __syncthreads();

    if (tid < 32) {
        const float* rr = &red[tid * 8];
        const float ssum = rr[0] + rr[1] + rr[2] + rr[3] + rr[4] + rr[5] + rr[6] + rr[7];
        out[row0 + tid] = softplus_stable(ssum + b3v);
    }
}

extern "C" void kernel_launch(void* const* d_in, const int* in_sizes, int n_in,
                              void* d_out, int out_size)
{
    const float* h   = (const float*)d_in[0];
    const void*  idx = (const void*)d_in[1];
    const float* W1  = (const float*)d_in[2];
    const float* b1  = (const float*)d_in[3];
    const float* W2  = (const float*)d_in[4];
    const float* b2  = (const float*)d_in[5];
    const float* W3  = (const float*)d_in[6];
    const float* b3  = (const float*)d_in[7];
    float*       out = (float*)d_out;

    void *ph, *pw1, *pw2;
    cudaGetSymbolAddress(&ph,  g_h);
    cudaGetSymbolAddress(&pw1, g_W1t);
    cudaGetSymbolAddress(&pw2, g_W2t);

    cvt_h_kernel<<<2048, 256>>>((__half*)ph, h, PB * PN * PD / 4);
    transpose_half_kernel<<<dim3(N1 / 32, K1 / 32), dim3(32, 8)>>>((__half*)pw1, W1, K1, N1);
    transpose_half_kernel<<<dim3(N2 / 32, K2 / 32), dim3(32, 8)>>>((__half*)pw2, W2, K2, N2);

    cudaFuncSetAttribute(precompute_y_kernel,
                         cudaFuncAttributeMaxDynamicSharedMemorySize, PRE_SMEM_BYTES);
    precompute_y_kernel<<<dim3(PB * PN / 128, 8), 512, PRE_SMEM_BYTES>>>();

    cudaFuncSetAttribute(swap_scoring_g,
                         cudaFuncAttributeMaxDynamicSharedMemorySize, SC_SMEM_BYTES);
    swap_scoring_g<<<NROWS / 32, 256, SC_SMEM_BYTES>>>(
        idx, b1, b2, W3, b3, out);
}